// round 3
// baseline (speedup 1.0000x reference)
#include <cuda_runtime.h>
#include <cuda_bf16.h>
#include <math.h>

// Shapes
#define BB 16
#define NN 256
#define DD 256
#define HH 8
#define HD 32
#define PD 4
#define RATIO 4
#define ROWS (BB*NN)            // 4096
#define PAIR_ROWS (BB*NN*NN)    // 1048576

// ---------------- scratch (device globals, no allocation) ----------------
__device__ float g_xn [ROWS*DD];        // 4 MB
__device__ float g_qkv[ROWS*3*DD];      // 12 MB
__device__ float g_biasT[BB*HH*NN*NN];  // 33.5 MB  [B,H,N,N]
__device__ float g_xa [ROWS*DD];        // 4 MB  [B,N,H*HD]
__device__ float g_x1 [ROWS*DD];        // 4 MB
__device__ float g_m1 [ROWS*RATIO*DD];  // 16 MB

__device__ __forceinline__ float gelu_exact(float x) {
    return 0.5f * x * (1.0f + erff(x * 0.70710678118654752f));
}

// ---------------- pairwise MLP: u[B,N,N,4] -> bias[B,H,N,N] ----------------
__global__ __launch_bounds__(256) void pairwise_kernel(
    const float* __restrict__ u,
    const float* __restrict__ w1, const float* __restrict__ b1,
    const float* __restrict__ w2, const float* __restrict__ b2,
    const float* __restrict__ w3, const float* __restrict__ b3,
    float* __restrict__ biasOut)
{
    __shared__ float w1s[4*64];
    __shared__ float b1s[64];
    __shared__ float w2t[64*64];   // transposed: w2t[j*64+i] = w2[i][j]
    __shared__ float b2s[64];
    __shared__ float w3s[64*8];
    __shared__ float b3s[8];

    int tid = threadIdx.x;
    if (tid < 64) { b1s[tid] = b1[tid]; b2s[tid] = b2[tid]; }
    if (tid < 8)  b3s[tid] = b3[tid];
    w1s[tid] = w1[tid];
    for (int i = tid; i < 512; i += 256) w3s[i] = w3[i];
    for (int i = tid; i < 4096; i += 256) {
        int j = i >> 6, ii = i & 63;
        w2t[i] = w2[ii*64 + j];
    }
    __syncthreads();

    int r = blockIdx.x * 256 + tid;    // row index in [B,N,N]
    float4 uv = ((const float4*)u)[r];

    float h1[64];
#pragma unroll
    for (int k = 0; k < 64; k++) {
        float t = b1s[k] + uv.x*w1s[k] + uv.y*w1s[64+k]
                        + uv.z*w1s[128+k] + uv.w*w1s[192+k];
        h1[k] = gelu_exact(t);
    }

    float acc[8];
#pragma unroll
    for (int h = 0; h < 8; h++) acc[h] = b3s[h];

#pragma unroll 8
    for (int j = 0; j < 64; j++) {
        float s = b2s[j];
        const float* wr = &w2t[j*64];
#pragma unroll
        for (int i2 = 0; i2 < 64; i2 += 4) {
            float4 w = *(const float4*)&wr[i2];
            s += h1[i2]*w.x + h1[i2+1]*w.y + h1[i2+2]*w.z + h1[i2+3]*w.w;
        }
        float g = gelu_exact(s);
#pragma unroll
        for (int h = 0; h < 8; h++) acc[h] += g * w3s[j*8 + h];
    }

    int b  = r >> 16;        // / (N*N)
    int rem = r & 65535;
    int i  = rem >> 8;
    int j  = rem & 255;
#pragma unroll
    for (int h = 0; h < 8; h++) {
        biasOut[(((b*8 + h)*256 + i) << 8) + j] = gelu_exact(acc[h]);
    }
}

// ---------------- LayerNorm: one block per row (D=256 threads) ----------------
__global__ __launch_bounds__(256) void ln_kernel(
    const float* __restrict__ x, const float* __restrict__ g,
    const float* __restrict__ bb, float* __restrict__ out)
{
    __shared__ float red[16];
    int r = blockIdx.x, t = threadIdx.x;
    float v = x[r*256 + t];

    float s = v;
#pragma unroll
    for (int o = 16; o > 0; o >>= 1) s += __shfl_xor_sync(0xffffffffu, s, o);
    if ((t & 31) == 0) red[t >> 5] = s;
    __syncthreads();
    float mu = 0.f;
#pragma unroll
    for (int w = 0; w < 8; w++) mu += red[w];
    mu *= (1.0f/256.0f);

    float d = v - mu;
    float q = d*d;
#pragma unroll
    for (int o = 16; o > 0; o >>= 1) q += __shfl_xor_sync(0xffffffffu, q, o);
    if ((t & 31) == 0) red[8 + (t >> 5)] = q;
    __syncthreads();
    float var = 0.f;
#pragma unroll
    for (int w = 0; w < 8; w++) var += red[8 + w];
    var *= (1.0f/256.0f);

    out[r*256 + t] = d * rsqrtf(var + 1e-5f) * g[t] + bb[t];
}

// ---------------- Tiled SGEMM: C[M,N] = epi(A[M,K] @ B[K,N] + bias, res) ------
// EPI: 0 = +bias ; 1 = gelu(+bias) ; 2 = +bias +res ; 3 = gelu(+bias)+res
template<int EPI>
__global__ __launch_bounds__(256) void sgemm_kernel(
    const float* __restrict__ A, const float* __restrict__ Bm,
    const float* __restrict__ bias, const float* __restrict__ res,
    float* __restrict__ C, int M, int Nn, int K)
{
    __shared__ float As[16][64];
    __shared__ float Bs[16][64];
    int tid = threadIdx.x;
    int tx = tid & 15, ty = tid >> 4;
    int row0 = blockIdx.y << 6, col0 = blockIdx.x << 6;
    int a_r = tid >> 2, a_c = (tid & 3) << 2;
    int b_r = tid >> 4, b_c = (tid & 15) << 2;

    float acc[4][4];
#pragma unroll
    for (int i = 0; i < 4; i++)
#pragma unroll
        for (int j = 0; j < 4; j++) acc[i][j] = 0.f;

    const float* Aptr = A + (long)(row0 + a_r)*K + a_c;
    const float* Bptr = Bm + (long)b_r*Nn + col0 + b_c;

    for (int k0 = 0; k0 < K; k0 += 16) {
        float4 av = *(const float4*)(Aptr + k0);
        As[a_c+0][a_r] = av.x; As[a_c+1][a_r] = av.y;
        As[a_c+2][a_r] = av.z; As[a_c+3][a_r] = av.w;
        float4 bv = *(const float4*)(Bptr + (long)k0*Nn);
        *(float4*)&Bs[b_r][b_c] = bv;
        __syncthreads();
#pragma unroll
        for (int k = 0; k < 16; k++) {
            float4 a4 = *(const float4*)&As[k][ty << 2];
            float4 b4 = *(const float4*)&Bs[k][tx << 2];
            float ar[4] = {a4.x, a4.y, a4.z, a4.w};
            float br[4] = {b4.x, b4.y, b4.z, b4.w};
#pragma unroll
            for (int i = 0; i < 4; i++)
#pragma unroll
                for (int j = 0; j < 4; j++)
                    acc[i][j] += ar[i] * br[j];
        }
        __syncthreads();
    }

#pragma unroll
    for (int i = 0; i < 4; i++) {
        int r = row0 + (ty << 2) + i;
#pragma unroll
        for (int j = 0; j < 4; j++) {
            int c = col0 + (tx << 2) + j;
            float v = acc[i][j] + bias[c];
            if (EPI == 1 || EPI == 3) v = gelu_exact(v);
            if (EPI == 2 || EPI == 3) v += res[(long)r*Nn + c];
            C[(long)r*Nn + c] = v;
        }
    }
}

// ---------------- Fused attention: per (b,h,64-row tile) ----------------
// qkv layout: [B*N, 3*256] with per-row [q(256) | k(256) | v(256)], head h at h*32
__global__ __launch_bounds__(256) void attn_kernel(
    const float* __restrict__ qkv, const float* __restrict__ biasT,
    const unsigned char* __restrict__ mask, float* __restrict__ xa)
{
    extern __shared__ float sm[];
    float* Ks = sm;                // 256*33
    float* Vs = Ks + 256*33;       // 256*33
    float* qs = Vs + 256*33;       // 32
    float* p  = qs + 32;           // 256
    float* red = p + 256;          // 16
    float* partial = red + 16;     // 256

    int tid = threadIdx.x;
    int blk = blockIdx.x;          // 512 blocks
    int bh = blk >> 2;
    int itile = blk & 3;
    int b = bh >> 3, h = bh & 7;

    for (int e = tid; e < 8192; e += 256) {
        int j = e >> 5, d = e & 31;
        const float* base = &qkv[(long)(b*256 + j)*768 + h*32 + d];
        Ks[j*33 + d] = base[256];
        Vs[j*33 + d] = base[512];
    }
    __syncthreads();

    const float scale = 0.17677669529663687f;   // 1/sqrt(32)
    bool masked = (mask[b*256 + tid] != 0);

    for (int ii = 0; ii < 64; ii++) {
        int i = itile*64 + ii;
        if (tid < 32) qs[tid] = qkv[(long)(b*256 + i)*768 + h*32 + tid];
        __syncthreads();

        float s = 0.f;
#pragma unroll
        for (int d = 0; d < 32; d++) s += qs[d] * Ks[tid*33 + d];
        s = s * scale + biasT[(long)((bh*256 + i) << 8) + tid];
        if (masked) s = -1e30f;

        // block max
        float m = s;
#pragma unroll
        for (int o = 16; o > 0; o >>= 1) m = fmaxf(m, __shfl_xor_sync(0xffffffffu, m, o));
        if ((tid & 31) == 0) red[tid >> 5] = m;
        __syncthreads();
        m = red[0];
#pragma unroll
        for (int w = 1; w < 8; w++) m = fmaxf(m, red[w]);

        float e = __expf(s - m);
        p[tid] = e;
        float z = e;
#pragma unroll
        for (int o = 16; o > 0; o >>= 1) z += __shfl_xor_sync(0xffffffffu, z, o);
        if ((tid & 31) == 0) red[8 + (tid >> 5)] = z;
        __syncthreads();
        z = 0.f;
#pragma unroll
        for (int w = 0; w < 8; w++) z += red[8 + w];

        // output: thread = (group g of 32 j's, hd)
        int hd = tid & 31, g = tid >> 5;
        float acc = 0.f;
#pragma unroll
        for (int jj = 0; jj < 32; jj++) {
            int j = g*32 + jj;
            acc += p[j] * Vs[j*33 + hd];
        }
        partial[g*32 + hd] = acc;
        __syncthreads();
        if (tid < 32) {
            float o = 0.f;
#pragma unroll
            for (int g2 = 0; g2 < 8; g2++) o += partial[g2*32 + tid];
            xa[(long)(b*256 + i)*256 + h*32 + tid] = o / z;
        }
        __syncthreads();
    }
}

// ---------------- launch ----------------
extern "C" void kernel_launch(void* const* d_in, const int* in_sizes, int n_in,
                              void* d_out, int out_size)
{
    const float* x      = (const float*)d_in[0];
    const float* u      = (const float*)d_in[1];
    const unsigned char* mask = (const unsigned char*)d_in[2];
    const float* n1_g   = (const float*)d_in[3];
    const float* n1_b   = (const float*)d_in[4];
    const float* qkv_w  = (const float*)d_in[5];
    const float* qkv_b  = (const float*)d_in[6];
    const float* proj_w = (const float*)d_in[7];
    const float* proj_b = (const float*)d_in[8];
    const float* n2_g   = (const float*)d_in[9];
    const float* n2_b   = (const float*)d_in[10];
    const float* mlp_w1 = (const float*)d_in[11];
    const float* mlp_b1 = (const float*)d_in[12];
    const float* mlp_w2 = (const float*)d_in[13];
    const float* mlp_b2 = (const float*)d_in[14];
    const float* pw_w1  = (const float*)d_in[15];
    const float* pw_b1  = (const float*)d_in[16];
    const float* pw_w2  = (const float*)d_in[17];
    const float* pw_b2  = (const float*)d_in[18];
    const float* pw_w3  = (const float*)d_in[19];
    const float* pw_b3  = (const float*)d_in[20];
    float* out = (float*)d_out;

    float *xn, *qkvb, *biasT, *xa, *x1, *m1;
    cudaGetSymbolAddress((void**)&xn,    g_xn);
    cudaGetSymbolAddress((void**)&qkvb,  g_qkv);
    cudaGetSymbolAddress((void**)&biasT, g_biasT);
    cudaGetSymbolAddress((void**)&xa,    g_xa);
    cudaGetSymbolAddress((void**)&x1,    g_x1);
    cudaGetSymbolAddress((void**)&m1,    g_m1);

    // 1. pairwise MLP -> bias[B,H,N,N]
    pairwise_kernel<<<PAIR_ROWS/256, 256>>>(u, pw_w1, pw_b1, pw_w2, pw_b2,
                                            pw_w3, pw_b3, biasT);
    // 2. LN1
    ln_kernel<<<ROWS, 256>>>(x, n1_g, n1_b, xn);
    // 3. QKV GEMM  [4096,256] x [256,768]
    sgemm_kernel<0><<<dim3(768/64, ROWS/64), 256>>>(xn, qkv_w, qkv_b, nullptr,
                                                    qkvb, ROWS, 768, 256);
    // 4. attention
    int attn_smem = (256*33*2 + 32 + 256 + 16 + 256) * sizeof(float);
    cudaFuncSetAttribute(attn_kernel, cudaFuncAttributeMaxDynamicSharedMemorySize,
                         attn_smem);
    attn_kernel<<<BB*HH*4, 256, attn_smem>>>(qkvb, biasT, mask, xa);
    // 5. proj + residual -> x1
    sgemm_kernel<2><<<dim3(256/64, ROWS/64), 256>>>(xa, proj_w, proj_b, x,
                                                    x1, ROWS, 256, 256);
    // 6. LN2
    ln_kernel<<<ROWS, 256>>>(x1, n2_g, n2_b, xn);
    // 7. MLP1 + gelu
    sgemm_kernel<1><<<dim3(1024/64, ROWS/64), 256>>>(xn, mlp_w1, mlp_b1, nullptr,
                                                     m1, ROWS, 1024, 256);
    // 8. MLP2 + gelu + residual -> out
    sgemm_kernel<3><<<dim3(256/64, ROWS/64), 256>>>(m1, mlp_w2, mlp_b2, x1,
                                                    out, ROWS, 256, 1024);
}

// round 5
// speedup vs baseline: 1.1590x; 1.1590x over previous
#include <cuda_runtime.h>
#include <cuda_bf16.h>
#include <math.h>

// Shapes
#define BB 16
#define NN 256
#define DD 256
#define HH 8
#define HD 32
#define PD 4
#define RATIO 4
#define ROWS (BB*NN)            // 4096
#define PAIR_ROWS (BB*NN*NN)    // 1048576

// ---------------- scratch (device globals, no allocation) ----------------
__device__ float g_xn [ROWS*DD];        // 4 MB
__device__ float g_qkv[ROWS*3*DD];      // 12 MB
__device__ float g_biasT[BB*HH*NN*NN];  // 33.5 MB  [B,H,N,N]
__device__ float g_xa [ROWS*DD];        // 4 MB  [B,N,H*HD]
__device__ float g_x1 [ROWS*DD];        // 4 MB
__device__ float g_m1 [ROWS*RATIO*DD];  // 16 MB

__device__ __forceinline__ float gelu_exact(float x) {
    return 0.5f * x * (1.0f + erff(x * 0.70710678118654752f));
}

// ---------------- pairwise MLP: u[B,N,N,4] -> bias[B,H,N,N] ----------------
__global__ __launch_bounds__(256) void pairwise_kernel(
    const float* __restrict__ u,
    const float* __restrict__ w1, const float* __restrict__ b1,
    const float* __restrict__ w2, const float* __restrict__ b2,
    const float* __restrict__ w3, const float* __restrict__ b3,
    float* __restrict__ biasOut)
{
    __shared__ float w1s[4*64];
    __shared__ float b1s[64];
    __shared__ float w2t[64*64];   // transposed: w2t[j*64+i] = w2[i][j]
    __shared__ float b2s[64];
    __shared__ float w3s[64*8];
    __shared__ float b3s[8];

    int tid = threadIdx.x;
    if (tid < 64) { b1s[tid] = b1[tid]; b2s[tid] = b2[tid]; }
    if (tid < 8)  b3s[tid] = b3[tid];
    w1s[tid] = w1[tid];
    for (int i = tid; i < 512; i += 256) w3s[i] = w3[i];
    for (int i = tid; i < 4096; i += 256) {
        int j = i >> 6, ii = i & 63;
        w2t[i] = w2[ii*64 + j];
    }
    __syncthreads();

    int r = blockIdx.x * 256 + tid;    // row index in [B,N,N]
    float4 uv = ((const float4*)u)[r];

    float h1[64];
#pragma unroll
    for (int k = 0; k < 64; k++) {
        float t = b1s[k] + uv.x*w1s[k] + uv.y*w1s[64+k]
                        + uv.z*w1s[128+k] + uv.w*w1s[192+k];
        h1[k] = gelu_exact(t);
    }

    float acc[8];
#pragma unroll
    for (int h = 0; h < 8; h++) acc[h] = b3s[h];

#pragma unroll 8
    for (int j = 0; j < 64; j++) {
        float s = b2s[j];
        const float* wr = &w2t[j*64];
#pragma unroll
        for (int i2 = 0; i2 < 64; i2 += 4) {
            float4 w = *(const float4*)&wr[i2];
            s += h1[i2]*w.x + h1[i2+1]*w.y + h1[i2+2]*w.z + h1[i2+3]*w.w;
        }
        float g = gelu_exact(s);
#pragma unroll
        for (int h = 0; h < 8; h++) acc[h] += g * w3s[j*8 + h];
    }

    int b  = r >> 16;        // / (N*N)
    int rem = r & 65535;
    int i  = rem >> 8;
    int j  = rem & 255;
#pragma unroll
    for (int h = 0; h < 8; h++) {
        biasOut[(((b*8 + h)*256 + i) << 8) + j] = gelu_exact(acc[h]);
    }
}

// ---------------- LayerNorm: one block per row (D=256 threads) ----------------
__global__ __launch_bounds__(256) void ln_kernel(
    const float* __restrict__ x, const float* __restrict__ g,
    const float* __restrict__ bb, float* __restrict__ out)
{
    __shared__ float red[16];
    int r = blockIdx.x, t = threadIdx.x;
    float v = x[r*256 + t];

    float s = v;
#pragma unroll
    for (int o = 16; o > 0; o >>= 1) s += __shfl_xor_sync(0xffffffffu, s, o);
    if ((t & 31) == 0) red[t >> 5] = s;
    __syncthreads();
    float mu = 0.f;
#pragma unroll
    for (int w = 0; w < 8; w++) mu += red[w];
    mu *= (1.0f/256.0f);

    float d = v - mu;
    float q = d*d;
#pragma unroll
    for (int o = 16; o > 0; o >>= 1) q += __shfl_xor_sync(0xffffffffu, q, o);
    if ((t & 31) == 0) red[8 + (t >> 5)] = q;
    __syncthreads();
    float var = 0.f;
#pragma unroll
    for (int w = 0; w < 8; w++) var += red[8 + w];
    var *= (1.0f/256.0f);

    out[r*256 + t] = d * rsqrtf(var + 1e-5f) * g[t] + bb[t];
}

// ---------------- Tiled SGEMM: C[M,N] = epi(A[M,K] @ B[K,N] + bias, res) ------
// EPI: 0 = +bias ; 1 = gelu(+bias) ; 2 = +bias +res ; 3 = gelu(+bias)+res
template<int EPI>
__global__ __launch_bounds__(256) void sgemm_kernel(
    const float* __restrict__ A, const float* __restrict__ Bm,
    const float* __restrict__ bias, const float* __restrict__ res,
    float* __restrict__ C, int M, int Nn, int K)
{
    __shared__ float As[16][64];
    __shared__ float Bs[16][64];
    int tid = threadIdx.x;
    int tx = tid & 15, ty = tid >> 4;
    int row0 = blockIdx.y << 6, col0 = blockIdx.x << 6;
    int a_r = tid >> 2, a_c = (tid & 3) << 2;
    int b_r = tid >> 4, b_c = (tid & 15) << 2;

    float acc[4][4];
#pragma unroll
    for (int i = 0; i < 4; i++)
#pragma unroll
        for (int j = 0; j < 4; j++) acc[i][j] = 0.f;

    const float* Aptr = A + (long)(row0 + a_r)*K + a_c;
    const float* Bptr = Bm + (long)b_r*Nn + col0 + b_c;

    for (int k0 = 0; k0 < K; k0 += 16) {
        float4 av = *(const float4*)(Aptr + k0);
        As[a_c+0][a_r] = av.x; As[a_c+1][a_r] = av.y;
        As[a_c+2][a_r] = av.z; As[a_c+3][a_r] = av.w;
        float4 bv = *(const float4*)(Bptr + (long)k0*Nn);
        *(float4*)&Bs[b_r][b_c] = bv;
        __syncthreads();
#pragma unroll
        for (int k = 0; k < 16; k++) {
            float4 a4 = *(const float4*)&As[k][ty << 2];
            float4 b4 = *(const float4*)&Bs[k][tx << 2];
            float ar[4] = {a4.x, a4.y, a4.z, a4.w};
            float br[4] = {b4.x, b4.y, b4.z, b4.w};
#pragma unroll
            for (int i = 0; i < 4; i++)
#pragma unroll
                for (int j = 0; j < 4; j++)
                    acc[i][j] += ar[i] * br[j];
        }
        __syncthreads();
    }

#pragma unroll
    for (int i = 0; i < 4; i++) {
        int r = row0 + (ty << 2) + i;
#pragma unroll
        for (int j = 0; j < 4; j++) {
            int c = col0 + (tx << 2) + j;
            float v = acc[i][j] + bias[c];
            if (EPI == 1 || EPI == 3) v = gelu_exact(v);
            if (EPI == 2 || EPI == 3) v += res[(long)r*Nn + c];
            C[(long)r*Nn + c] = v;
        }
    }
}

// ---------------- Fused attention v2: warp-autonomous, one block per (b,h) ---
// grid = 128 (B*H), block = 512 (16 warps). Each warp owns 16 query rows,
// processed in pairs (K/V smem reads amortized over 2 rows). No block
// barriers after the K/V stage; all reductions are warp shuffles.
// smem: K[256*36] + V[256*36] + P[16 warps * 2 rows * 256] = 104 KB.
#define KVSTRIDE 36
__global__ __launch_bounds__(512) void attn_kernel(
    const float* __restrict__ qkv, const float* __restrict__ biasT,
    const unsigned char* __restrict__ mask, float* __restrict__ xa)
{
    extern __shared__ float sm[];
    float* Ks = sm;                        // 256*36
    float* Vs = Ks + 256*KVSTRIDE;         // 256*36
    float* Ps = Vs + 256*KVSTRIDE;         // 16*512

    int tid  = threadIdx.x;
    int warp = tid >> 5, lane = tid & 31;
    int bh = blockIdx.x;
    int b = bh >> 3, h = bh & 7;

    const float* base = qkv + (long)b*256*768 + h*32;

    // stage K, V (each row padded to 36 floats -> conflict-free row & col reads)
    for (int idx = tid; idx < 2048; idx += 512) {
        int row = idx >> 3, d4 = (idx & 7) << 2;
        const float* src = base + (long)row*768;
        *(float4*)&Ks[row*KVSTRIDE + d4] = *(const float4*)(src + 256 + d4);
        *(float4*)&Vs[row*KVSTRIDE + d4] = *(const float4*)(src + 512 + d4);
    }
    __syncthreads();

    // per-lane key mask bits: key j = c*32 + lane
    unsigned mk = 0;
#pragma unroll
    for (int c = 0; c < 8; c++)
        if (mask[b*256 + c*32 + lane]) mk |= (1u << c);

    float* p0 = Ps + warp*512;
    float* p1 = p0 + 256;
    const float scale = 0.17677669529663687f;   // 1/sqrt(32)

    for (int ii = 0; ii < 16; ii += 2) {
        int i0 = warp*16 + ii, i1 = i0 + 1;

        // q for both rows -> registers (uniform per warp, broadcast loads)
        float q0[32], q1[32];
        const float* q0p = base + (long)i0*768;
        const float* q1p = base + (long)i1*768;
#pragma unroll
        for (int d4 = 0; d4 < 8; d4++) {
            float4 t0 = *(const float4*)(q0p + 4*d4);
            q0[4*d4]=t0.x; q0[4*d4+1]=t0.y; q0[4*d4+2]=t0.z; q0[4*d4+3]=t0.w;
            float4 t1 = *(const float4*)(q1p + 4*d4);
            q1[4*d4]=t1.x; q1[4*d4+1]=t1.y; q1[4*d4+2]=t1.z; q1[4*d4+3]=t1.w;
        }

        // bias rows (prefetch into regs; coalesced 128B per chunk)
        const float* br0 = biasT + ((long)(bh*256 + i0) << 8);
        const float* br1 = biasT + ((long)(bh*256 + i1) << 8);
        float s0[8], s1[8];
#pragma unroll
        for (int c = 0; c < 8; c++) {
            s0[c] = br0[c*32 + lane];
            s1[c] = br1[c*32 + lane];
        }

        // scores: lane owns keys {c*32+lane}
#pragma unroll
        for (int c = 0; c < 8; c++) {
            const float4* kr = (const float4*)&Ks[(c*32 + lane)*KVSTRIDE];
            float a0 = 0.f, a1 = 0.f;
#pragma unroll
            for (int d4 = 0; d4 < 8; d4++) {
                float4 k4 = kr[d4];
                a0 += q0[4*d4]*k4.x + q0[4*d4+1]*k4.y + q0[4*d4+2]*k4.z + q0[4*d4+3]*k4.w;
                a1 += q1[4*d4]*k4.x + q1[4*d4+1]*k4.y + q1[4*d4+2]*k4.z + q1[4*d4+3]*k4.w;
            }
            s0[c] += a0 * scale;
            s1[c] += a1 * scale;
            if ((mk >> c) & 1) { s0[c] = -1e30f; s1[c] = -1e30f; }
        }

        // softmax (warp-local)
        float m0 = s0[0], m1 = s1[0];
#pragma unroll
        for (int c = 1; c < 8; c++) { m0 = fmaxf(m0, s0[c]); m1 = fmaxf(m1, s1[c]); }
#pragma unroll
        for (int o = 16; o > 0; o >>= 1) {
            m0 = fmaxf(m0, __shfl_xor_sync(0xffffffffu, m0, o));
            m1 = fmaxf(m1, __shfl_xor_sync(0xffffffffu, m1, o));
        }
        float z0 = 0.f, z1 = 0.f;
#pragma unroll
        for (int c = 0; c < 8; c++) {
            s0[c] = __expf(s0[c] - m0);  z0 += s0[c];
            s1[c] = __expf(s1[c] - m1);  z1 += s1[c];
        }
#pragma unroll
        for (int o = 16; o > 0; o >>= 1) {
            z0 += __shfl_xor_sync(0xffffffffu, z0, o);
            z1 += __shfl_xor_sync(0xffffffffu, z1, o);
        }
        float rz0 = 1.0f / z0, rz1 = 1.0f / z1;

        // exchange p through per-warp smem
#pragma unroll
        for (int c = 0; c < 8; c++) { p0[c*32 + lane] = s0[c]; p1[c*32 + lane] = s1[c]; }
        __syncwarp();

        // PV: lane owns output dim d = lane; V reads shared across both rows
        float acc0 = 0.f, acc1 = 0.f;
        const float4* p04 = (const float4*)p0;
        const float4* p14 = (const float4*)p1;
#pragma unroll
        for (int c = 0; c < 8; c++) {
#pragma unroll
            for (int j4 = 0; j4 < 8; j4++) {
                float4 P0 = p04[c*8 + j4];
                float4 P1 = p14[c*8 + j4];
                int j = c*32 + j4*4;
                float v0 = Vs[(j+0)*KVSTRIDE + lane];
                float v1 = Vs[(j+1)*KVSTRIDE + lane];
                float v2 = Vs[(j+2)*KVSTRIDE + lane];
                float v3 = Vs[(j+3)*KVSTRIDE + lane];
                acc0 += P0.x*v0 + P0.y*v1 + P0.z*v2 + P0.w*v3;
                acc1 += P1.x*v0 + P1.y*v1 + P1.z*v2 + P1.w*v3;
            }
        }
        __syncwarp();   // protect p buffers before next iteration overwrites

        xa[(long)(b*256 + i0)*256 + h*32 + lane] = acc0 * rz0;
        xa[(long)(b*256 + i1)*256 + h*32 + lane] = acc1 * rz1;
    }
}

// ---------------- launch ----------------
extern "C" void kernel_launch(void* const* d_in, const int* in_sizes, int n_in,
                              void* d_out, int out_size)
{
    const float* x      = (const float*)d_in[0];
    const float* u      = (const float*)d_in[1];
    const unsigned char* mask = (const unsigned char*)d_in[2];
    const float* n1_g   = (const float*)d_in[3];
    const float* n1_b   = (const float*)d_in[4];
    const float* qkv_w  = (const float*)d_in[5];
    const float* qkv_b  = (const float*)d_in[6];
    const float* proj_w = (const float*)d_in[7];
    const float* proj_b = (const float*)d_in[8];
    const float* n2_g   = (const float*)d_in[9];
    const float* n2_b   = (const float*)d_in[10];
    const float* mlp_w1 = (const float*)d_in[11];
    const float* mlp_b1 = (const float*)d_in[12];
    const float* mlp_w2 = (const float*)d_in[13];
    const float* mlp_b2 = (const float*)d_in[14];
    const float* pw_w1  = (const float*)d_in[15];
    const float* pw_b1  = (const float*)d_in[16];
    const float* pw_w2  = (const float*)d_in[17];
    const float* pw_b2  = (const float*)d_in[18];
    const float* pw_w3  = (const float*)d_in[19];
    const float* pw_b3  = (const float*)d_in[20];
    float* out = (float*)d_out;

    float *xn, *qkvb, *biasT, *xa, *x1, *m1;
    cudaGetSymbolAddress((void**)&xn,    g_xn);
    cudaGetSymbolAddress((void**)&qkvb,  g_qkv);
    cudaGetSymbolAddress((void**)&biasT, g_biasT);
    cudaGetSymbolAddress((void**)&xa,    g_xa);
    cudaGetSymbolAddress((void**)&x1,    g_x1);
    cudaGetSymbolAddress((void**)&m1,    g_m1);

    // 1. pairwise MLP -> bias[B,H,N,N]
    pairwise_kernel<<<PAIR_ROWS/256, 256>>>(u, pw_w1, pw_b1, pw_w2, pw_b2,
                                            pw_w3, pw_b3, biasT);
    // 2. LN1
    ln_kernel<<<ROWS, 256>>>(x, n1_g, n1_b, xn);
    // 3. QKV GEMM  [4096,256] x [256,768]
    sgemm_kernel<0><<<dim3(768/64, ROWS/64), 256>>>(xn, qkv_w, qkv_b, nullptr,
                                                    qkvb, ROWS, 768, 256);
    // 4. attention (warp-autonomous)
    int attn_smem = (256*KVSTRIDE*2 + 16*512) * sizeof(float);
    cudaFuncSetAttribute(attn_kernel, cudaFuncAttributeMaxDynamicSharedMemorySize,
                         attn_smem);
    attn_kernel<<<BB*HH, 512, attn_smem>>>(qkvb, biasT, mask, xa);
    // 5. proj + residual -> x1
    sgemm_kernel<2><<<dim3(256/64, ROWS/64), 256>>>(xa, proj_w, proj_b, x,
                                                    x1, ROWS, 256, 256);
    // 6. LN2
    ln_kernel<<<ROWS, 256>>>(x1, n2_g, n2_b, xn);
    // 7. MLP1 + gelu
    sgemm_kernel<1><<<dim3(1024/64, ROWS/64), 256>>>(xn, mlp_w1, mlp_b1, nullptr,
                                                     m1, ROWS, 1024, 256);
    // 8. MLP2 + gelu + residual -> out
    sgemm_kernel<3><<<dim3(256/64, ROWS/64), 256>>>(m1, mlp_w2, mlp_b2, x1,
                                                    out, ROWS, 256, 1024);
}

// round 7
// speedup vs baseline: 1.4692x; 1.2676x over previous
#include <cuda_runtime.h>
#include <cuda_bf16.h>
#include <math.h>

// Shapes
#define BB 16
#define NN 256
#define DD 256
#define HH 8
#define HD 32
#define PD 4
#define RATIO 4
#define ROWS (BB*NN)            // 4096
#define PAIR_ROWS (BB*NN*NN)    // 1048576

// ---------------- scratch (device globals, no allocation) ----------------
__device__ float g_xn [ROWS*DD];        // 4 MB
__device__ float g_qkv[ROWS*3*DD];      // 12 MB
__device__ float g_biasT[BB*HH*NN*NN];  // 33.5 MB  [B,H,N,N]
__device__ float g_xa [ROWS*DD];        // 4 MB  [B,N,H*HD]
__device__ float g_x1 [ROWS*DD];        // 4 MB
__device__ float g_m1 [ROWS*RATIO*DD];  // 16 MB

__device__ __forceinline__ float gelu_exact(float x) {
    return 0.5f * x * (1.0f + erff(x * 0.70710678118654752f));
}

__device__ __forceinline__ unsigned f2tf32(float x) {
    unsigned r;
    asm("cvt.rna.tf32.f32 %0, %1;" : "=r"(r) : "f"(x));
    return r;
}

__device__ __forceinline__ void mma_tf32(
    float& c0, float& c1, float& c2, float& c3,
    unsigned a0, unsigned a1, unsigned a2, unsigned a3,
    unsigned b0, unsigned b1)
{
    asm volatile(
        "mma.sync.aligned.m16n8k8.row.col.f32.tf32.tf32.f32 "
        "{%0,%1,%2,%3}, {%4,%5,%6,%7}, {%8,%9}, {%0,%1,%2,%3};"
        : "+f"(c0), "+f"(c1), "+f"(c2), "+f"(c3)
        : "r"(a0), "r"(a1), "r"(a2), "r"(a3), "r"(b0), "r"(b1));
}

// ---------------- pairwise MLP v2 (tf32 tensor cores) ----------------
// u[B,N,N,4] -> bias[B,H,N,N].  Block = 256 thr / 128 rows, grid = 8192.
// h1 (1Mx64) scalar; h2 = gelu(h1 @ w2 + b2) via mma.sync tf32;
// h3 = gelu(h2 @ w3 + b3) in-register with quad-lane reduction.
#define H1S 68   // smem row stride for h1 (conflict-free fragment loads)
__global__ __launch_bounds__(256) void pairwise_kernel(
    const float* __restrict__ u,
    const float* __restrict__ w1, const float* __restrict__ b1,
    const float* __restrict__ w2, const float* __restrict__ b2,
    const float* __restrict__ w3, const float* __restrict__ b3,
    float* __restrict__ biasOut)
{
    extern __shared__ float dsm[];
    unsigned* h1s = (unsigned*)dsm;                 // 128*68
    unsigned* w2f = h1s + 128*H1S;                  // 4096 (fragment layout)
    float*    w3s = (float*)(w2f + 4096);           // 512
    float*    b2s = w3s + 512;                      // 64
    float*    b3s = b2s + 64;                       // 8
    float*    w1s = b3s + 8;                        // 256
    float*    b1s = w1s + 256;                      // 64

    int tid = threadIdx.x;
    int lane = tid & 31, warp = tid >> 5;
    int tig = lane & 3, gid = lane >> 2;

    // ---- stage weights ----
    if (tid < 64)  b1s[tid] = b1[tid];
    if (tid < 64)  b2s[tid] = b2[tid];
    if (tid < 8)   b3s[tid] = b3[tid];
    w1s[tid] = w1[tid];
    for (int i = tid; i < 512; i += 256) w3s[i] = w3[i];
    // w2 -> fragment-ready tf32 layout: uint2 per (kt,nt,lane)
    for (int idx = tid; idx < 4096; idx += 256) {
        int tile = idx >> 6;          // kt*8 + nt
        int pos  = idx & 63;
        int l    = pos >> 1, which = pos & 1;
        int kt = tile >> 3, nt = tile & 7;
        int ltig = l & 3, lgid = l >> 2;
        int k = kt*8 + ltig + which*4;
        int n = nt*8 + lgid;
        w2f[tile*64 + l*2 + which] = f2tf32(w2[k*64 + n]);
    }

    // ---- h1 = gelu(u @ w1 + b1), tf32-rounded into smem ----
    {
        int row = tid >> 1;                 // 0..127
        int c0  = (tid & 1) * 32;
        long gr = (long)blockIdx.x * 128 + row;
        float4 uv = ((const float4*)u)[gr];
        unsigned* dst = h1s + row*H1S + c0;
#pragma unroll
        for (int cc = 0; cc < 32; cc += 4) {
            unsigned pk[4];
#pragma unroll
            for (int q = 0; q < 4; q++) {
                int c = c0 + cc + q;
                float t = b1s[c] + uv.x*w1s[c] + uv.y*w1s[64+c]
                                 + uv.z*w1s[128+c] + uv.w*w1s[192+c];
                pk[q] = f2tf32(gelu_exact(t));
            }
            *(uint4*)&dst[cc] = make_uint4(pk[0], pk[1], pk[2], pk[3]);
        }
    }
    __syncthreads();

    // ---- h2 = h1 @ w2 via mma (warp owns 16 rows) ----
    float c[8][4];
#pragma unroll
    for (int nt = 0; nt < 8; nt++)
#pragma unroll
        for (int q = 0; q < 4; q++) c[nt][q] = 0.f;

    const unsigned* h1w = h1s + (warp*16 + gid)*H1S;
#pragma unroll
    for (int kt = 0; kt < 8; kt++) {
        unsigned a0 = h1w[kt*8 + tig];
        unsigned a1 = h1w[8*H1S + kt*8 + tig];
        unsigned a2 = h1w[kt*8 + tig + 4];
        unsigned a3 = h1w[8*H1S + kt*8 + tig + 4];
        const uint2* bf = (const uint2*)(w2f + kt*8*64);
#pragma unroll
        for (int nt = 0; nt < 8; nt++) {
            uint2 b = bf[nt*32 + lane];
            mma_tf32(c[nt][0], c[nt][1], c[nt][2], c[nt][3],
                     a0, a1, a2, a3, b.x, b.y);
        }
    }

    // ---- epilogue: gelu(h2 + b2), contract with w3, reduce, gelu, store ----
    float acc0[8], acc1[8];
#pragma unroll
    for (int h = 0; h < 8; h++) { acc0[h] = 0.f; acc1[h] = 0.f; }

#pragma unroll
    for (int nt = 0; nt < 8; nt++) {
        int col0 = nt*8 + tig*2;
        float g00 = gelu_exact(c[nt][0] + b2s[col0]);
        float g01 = gelu_exact(c[nt][1] + b2s[col0+1]);
        float g10 = gelu_exact(c[nt][2] + b2s[col0]);
        float g11 = gelu_exact(c[nt][3] + b2s[col0+1]);
        const float4* w3r = (const float4*)&w3s[col0*8];
        float4 wa0 = w3r[0], wa1 = w3r[1];   // w3[col0][0..7]
        float4 wb0 = w3r[2], wb1 = w3r[3];   // w3[col0+1][0..7]
        acc0[0] += g00*wa0.x + g01*wb0.x;  acc1[0] += g10*wa0.x + g11*wb0.x;
        acc0[1] += g00*wa0.y + g01*wb0.y;  acc1[1] += g10*wa0.y + g11*wb0.y;
        acc0[2] += g00*wa0.z + g01*wb0.z;  acc1[2] += g10*wa0.z + g11*wb0.z;
        acc0[3] += g00*wa0.w + g01*wb0.w;  acc1[3] += g10*wa0.w + g11*wb0.w;
        acc0[4] += g00*wa1.x + g01*wb1.x;  acc1[4] += g10*wa1.x + g11*wb1.x;
        acc0[5] += g00*wa1.y + g01*wb1.y;  acc1[5] += g10*wa1.y + g11*wb1.y;
        acc0[6] += g00*wa1.z + g01*wb1.z;  acc1[6] += g10*wa1.z + g11*wb1.z;
        acc0[7] += g00*wa1.w + g01*wb1.w;  acc1[7] += g10*wa1.w + g11*wb1.w;
    }

    // reduce over the 4 quad lanes (tig bits = lane bits 0,1)
#pragma unroll
    for (int h = 0; h < 8; h++) {
        acc0[h] += __shfl_xor_sync(0xffffffffu, acc0[h], 1);
        acc1[h] += __shfl_xor_sync(0xffffffffu, acc1[h], 1);
    }
#pragma unroll
    for (int h = 0; h < 8; h++) {
        acc0[h] += __shfl_xor_sync(0xffffffffu, acc0[h], 2);
        acc1[h] += __shfl_xor_sync(0xffffffffu, acc1[h], 2);
    }

    long R0 = (long)blockIdx.x * 128 + warp*16 + gid;   // row for acc0
    long R1 = R0 + 8;                                   // row for acc1
    int b = (int)(R0 >> 16);
    int i = (int)((R0 >> 8) & 255);
    int j0 = (int)(R0 & 255);
    int hA = tig*2, hB = hA + 1;

    float oA0 = gelu_exact(acc0[hA] + b3s[hA]);
    float oB0 = gelu_exact(acc0[hB] + b3s[hB]);
    float oA1 = gelu_exact(acc1[hA] + b3s[hA]);
    float oB1 = gelu_exact(acc1[hB] + b3s[hB]);

    long baseA = ((long)(b*8 + hA) << 16) + (i << 8);
    long baseB = ((long)(b*8 + hB) << 16) + (i << 8);
    biasOut[baseA + j0]     = oA0;
    biasOut[baseB + j0]     = oB0;
    biasOut[baseA + j0 + 8] = oA1;
    biasOut[baseB + j0 + 8] = oB1;
}

// ---------------- LayerNorm: one block per row (D=256 threads) ----------------
__global__ __launch_bounds__(256) void ln_kernel(
    const float* __restrict__ x, const float* __restrict__ g,
    const float* __restrict__ bb, float* __restrict__ out)
{
    __shared__ float red[16];
    int r = blockIdx.x, t = threadIdx.x;
    float v = x[r*256 + t];

    float s = v;
#pragma unroll
    for (int o = 16; o > 0; o >>= 1) s += __shfl_xor_sync(0xffffffffu, s, o);
    if ((t & 31) == 0) red[t >> 5] = s;
    __syncthreads();
    float mu = 0.f;
#pragma unroll
    for (int w = 0; w < 8; w++) mu += red[w];
    mu *= (1.0f/256.0f);

    float d = v - mu;
    float q = d*d;
#pragma unroll
    for (int o = 16; o > 0; o >>= 1) q += __shfl_xor_sync(0xffffffffu, q, o);
    if ((t & 31) == 0) red[8 + (t >> 5)] = q;
    __syncthreads();
    float var = 0.f;
#pragma unroll
    for (int w = 0; w < 8; w++) var += red[8 + w];
    var *= (1.0f/256.0f);

    out[r*256 + t] = d * rsqrtf(var + 1e-5f) * g[t] + bb[t];
}

// ---------------- Tiled SGEMM: C[M,N] = epi(A[M,K] @ B[K,N] + bias, res) ------
// EPI: 0 = +bias ; 1 = gelu(+bias) ; 2 = +bias +res ; 3 = gelu(+bias)+res
template<int EPI>
__global__ __launch_bounds__(256) void sgemm_kernel(
    const float* __restrict__ A, const float* __restrict__ Bm,
    const float* __restrict__ bias, const float* __restrict__ res,
    float* __restrict__ C, int M, int Nn, int K)
{
    __shared__ float As[16][64];
    __shared__ float Bs[16][64];
    int tid = threadIdx.x;
    int tx = tid & 15, ty = tid >> 4;
    int row0 = blockIdx.y << 6, col0 = blockIdx.x << 6;
    int a_r = tid >> 2, a_c = (tid & 3) << 2;
    int b_r = tid >> 4, b_c = (tid & 15) << 2;

    float acc[4][4];
#pragma unroll
    for (int i = 0; i < 4; i++)
#pragma unroll
        for (int j = 0; j < 4; j++) acc[i][j] = 0.f;

    const float* Aptr = A + (long)(row0 + a_r)*K + a_c;
    const float* Bptr = Bm + (long)b_r*Nn + col0 + b_c;

    for (int k0 = 0; k0 < K; k0 += 16) {
        float4 av = *(const float4*)(Aptr + k0);
        As[a_c+0][a_r] = av.x; As[a_c+1][a_r] = av.y;
        As[a_c+2][a_r] = av.z; As[a_c+3][a_r] = av.w;
        float4 bv = *(const float4*)(Bptr + (long)k0*Nn);
        *(float4*)&Bs[b_r][b_c] = bv;
        __syncthreads();
#pragma unroll
        for (int k = 0; k < 16; k++) {
            float4 a4 = *(const float4*)&As[k][ty << 2];
            float4 b4 = *(const float4*)&Bs[k][tx << 2];
            float ar[4] = {a4.x, a4.y, a4.z, a4.w};
            float br[4] = {b4.x, b4.y, b4.z, b4.w};
#pragma unroll
            for (int i = 0; i < 4; i++)
#pragma unroll
                for (int j = 0; j < 4; j++)
                    acc[i][j] += ar[i] * br[j];
        }
        __syncthreads();
    }

#pragma unroll
    for (int i = 0; i < 4; i++) {
        int r = row0 + (ty << 2) + i;
#pragma unroll
        for (int j = 0; j < 4; j++) {
            int c = col0 + (tx << 2) + j;
            float v = acc[i][j] + bias[c];
            if (EPI == 1 || EPI == 3) v = gelu_exact(v);
            if (EPI == 2 || EPI == 3) v += res[(long)r*Nn + c];
            C[(long)r*Nn + c] = v;
        }
    }
}

// ---------------- Fused attention v2: warp-autonomous, one block per (b,h) ---
#define KVSTRIDE 36
__global__ __launch_bounds__(512) void attn_kernel(
    const float* __restrict__ qkv, const float* __restrict__ biasT,
    const unsigned char* __restrict__ mask, float* __restrict__ xa)
{
    extern __shared__ float sm[];
    float* Ks = sm;                        // 256*36
    float* Vs = Ks + 256*KVSTRIDE;         // 256*36
    float* Ps = Vs + 256*KVSTRIDE;         // 16*512

    int tid  = threadIdx.x;
    int warp = tid >> 5, lane = tid & 31;
    int bh = blockIdx.x;
    int b = bh >> 3, h = bh & 7;

    const float* base = qkv + (long)b*256*768 + h*32;

    for (int idx = tid; idx < 2048; idx += 512) {
        int row = idx >> 3, d4 = (idx & 7) << 2;
        const float* src = base + (long)row*768;
        *(float4*)&Ks[row*KVSTRIDE + d4] = *(const float4*)(src + 256 + d4);
        *(float4*)&Vs[row*KVSTRIDE + d4] = *(const float4*)(src + 512 + d4);
    }
    __syncthreads();

    unsigned mk = 0;
#pragma unroll
    for (int c = 0; c < 8; c++)
        if (mask[b*256 + c*32 + lane]) mk |= (1u << c);

    float* p0 = Ps + warp*512;
    float* p1 = p0 + 256;
    const float scale = 0.17677669529663687f;   // 1/sqrt(32)

    for (int ii = 0; ii < 16; ii += 2) {
        int i0 = warp*16 + ii, i1 = i0 + 1;

        float q0[32], q1[32];
        const float* q0p = base + (long)i0*768;
        const float* q1p = base + (long)i1*768;
#pragma unroll
        for (int d4 = 0; d4 < 8; d4++) {
            float4 t0 = *(const float4*)(q0p + 4*d4);
            q0[4*d4]=t0.x; q0[4*d4+1]=t0.y; q0[4*d4+2]=t0.z; q0[4*d4+3]=t0.w;
            float4 t1 = *(const float4*)(q1p + 4*d4);
            q1[4*d4]=t1.x; q1[4*d4+1]=t1.y; q1[4*d4+2]=t1.z; q1[4*d4+3]=t1.w;
        }

        const float* br0 = biasT + ((long)(bh*256 + i0) << 8);
        const float* br1 = biasT + ((long)(bh*256 + i1) << 8);
        float s0[8], s1[8];
#pragma unroll
        for (int c = 0; c < 8; c++) {
            s0[c] = br0[c*32 + lane];
            s1[c] = br1[c*32 + lane];
        }

#pragma unroll
        for (int c = 0; c < 8; c++) {
            const float4* kr = (const float4*)&Ks[(c*32 + lane)*KVSTRIDE];
            float a0 = 0.f, a1 = 0.f;
#pragma unroll
            for (int d4 = 0; d4 < 8; d4++) {
                float4 k4 = kr[d4];
                a0 += q0[4*d4]*k4.x + q0[4*d4+1]*k4.y + q0[4*d4+2]*k4.z + q0[4*d4+3]*k4.w;
                a1 += q1[4*d4]*k4.x + q1[4*d4+1]*k4.y + q1[4*d4+2]*k4.z + q1[4*d4+3]*k4.w;
            }
            s0[c] += a0 * scale;
            s1[c] += a1 * scale;
            if ((mk >> c) & 1) { s0[c] = -1e30f; s1[c] = -1e30f; }
        }

        float m0 = s0[0], m1 = s1[0];
#pragma unroll
        for (int c = 1; c < 8; c++) { m0 = fmaxf(m0, s0[c]); m1 = fmaxf(m1, s1[c]); }
#pragma unroll
        for (int o = 16; o > 0; o >>= 1) {
            m0 = fmaxf(m0, __shfl_xor_sync(0xffffffffu, m0, o));
            m1 = fmaxf(m1, __shfl_xor_sync(0xffffffffu, m1, o));
        }
        float z0 = 0.f, z1 = 0.f;
#pragma unroll
        for (int c = 0; c < 8; c++) {
            s0[c] = __expf(s0[c] - m0);  z0 += s0[c];
            s1[c] = __expf(s1[c] - m1);  z1 += s1[c];
        }
#pragma unroll
        for (int o = 16; o > 0; o >>= 1) {
            z0 += __shfl_xor_sync(0xffffffffu, z0, o);
            z1 += __shfl_xor_sync(0xffffffffu, z1, o);
        }
        float rz0 = 1.0f / z0, rz1 = 1.0f / z1;

#pragma unroll
        for (int c = 0; c < 8; c++) { p0[c*32 + lane] = s0[c]; p1[c*32 + lane] = s1[c]; }
        __syncwarp();

        float acc0 = 0.f, acc1 = 0.f;
        const float4* p04 = (const float4*)p0;
        const float4* p14 = (const float4*)p1;
#pragma unroll
        for (int c = 0; c < 8; c++) {
#pragma unroll
            for (int j4 = 0; j4 < 8; j4++) {
                float4 P0 = p04[c*8 + j4];
                float4 P1 = p14[c*8 + j4];
                int j = c*32 + j4*4;
                float v0 = Vs[(j+0)*KVSTRIDE + lane];
                float v1 = Vs[(j+1)*KVSTRIDE + lane];
                float v2 = Vs[(j+2)*KVSTRIDE + lane];
                float v3 = Vs[(j+3)*KVSTRIDE + lane];
                acc0 += P0.x*v0 + P0.y*v1 + P0.z*v2 + P0.w*v3;
                acc1 += P1.x*v0 + P1.y*v1 + P1.z*v2 + P1.w*v3;
            }
        }
        __syncwarp();

        xa[(long)(b*256 + i0)*256 + h*32 + lane] = acc0 * rz0;
        xa[(long)(b*256 + i1)*256 + h*32 + lane] = acc1 * rz1;
    }
}

// ---------------- launch ----------------
extern "C" void kernel_launch(void* const* d_in, const int* in_sizes, int n_in,
                              void* d_out, int out_size)
{
    const float* x      = (const float*)d_in[0];
    const float* u      = (const float*)d_in[1];
    const unsigned char* mask = (const unsigned char*)d_in[2];
    const float* n1_g   = (const float*)d_in[3];
    const float* n1_b   = (const float*)d_in[4];
    const float* qkv_w  = (const float*)d_in[5];
    const float* qkv_b  = (const float*)d_in[6];
    const float* proj_w = (const float*)d_in[7];
    const float* proj_b = (const float*)d_in[8];
    const float* n2_g   = (const float*)d_in[9];
    const float* n2_b   = (const float*)d_in[10];
    const float* mlp_w1 = (const float*)d_in[11];
    const float* mlp_b1 = (const float*)d_in[12];
    const float* mlp_w2 = (const float*)d_in[13];
    const float* mlp_b2 = (const float*)d_in[14];
    const float* pw_w1  = (const float*)d_in[15];
    const float* pw_b1  = (const float*)d_in[16];
    const float* pw_w2  = (const float*)d_in[17];
    const float* pw_b2  = (const float*)d_in[18];
    const float* pw_w3  = (const float*)d_in[19];
    const float* pw_b3  = (const float*)d_in[20];
    float* out = (float*)d_out;

    float *xn, *qkvb, *biasT, *xa, *x1, *m1;
    cudaGetSymbolAddress((void**)&xn,    g_xn);
    cudaGetSymbolAddress((void**)&qkvb,  g_qkv);
    cudaGetSymbolAddress((void**)&biasT, g_biasT);
    cudaGetSymbolAddress((void**)&xa,    g_xa);
    cudaGetSymbolAddress((void**)&x1,    g_x1);
    cudaGetSymbolAddress((void**)&m1,    g_m1);

    // 1. pairwise MLP (tf32 mma) -> bias[B,H,N,N]
    int pw_smem = (128*H1S + 4096 + 512 + 64 + 8 + 256 + 64) * 4;
    cudaFuncSetAttribute(pairwise_kernel,
                         cudaFuncAttributeMaxDynamicSharedMemorySize, pw_smem);
    pairwise_kernel<<<PAIR_ROWS/128, 256, pw_smem>>>(u, pw_w1, pw_b1, pw_w2, pw_b2,
                                                     pw_w3, pw_b3, biasT);
    // 2. LN1
    ln_kernel<<<ROWS, 256>>>(x, n1_g, n1_b, xn);
    // 3. QKV GEMM  [4096,256] x [256,768]
    sgemm_kernel<0><<<dim3(768/64, ROWS/64), 256>>>(xn, qkv_w, qkv_b, nullptr,
                                                    qkvb, ROWS, 768, 256);
    // 4. attention (warp-autonomous)
    int attn_smem = (256*KVSTRIDE*2 + 16*512) * sizeof(float);
    cudaFuncSetAttribute(attn_kernel, cudaFuncAttributeMaxDynamicSharedMemorySize,
                         attn_smem);
    attn_kernel<<<BB*HH, 512, attn_smem>>>(qkvb, biasT, mask, xa);
    // 5. proj + residual -> x1
    sgemm_kernel<2><<<dim3(256/64, ROWS/64), 256>>>(xa, proj_w, proj_b, x,
                                                    x1, ROWS, 256, 256);
    // 6. LN2
    ln_kernel<<<ROWS, 256>>>(x1, n2_g, n2_b, xn);
    // 7. MLP1 + gelu
    sgemm_kernel<1><<<dim3(1024/64, ROWS/64), 256>>>(xn, mlp_w1, mlp_b1, nullptr,
                                                     m1, ROWS, 1024, 256);
    // 8. MLP2 + gelu + residual -> out
    sgemm_kernel<3><<<dim3(256/64, ROWS/64), 256>>>(m1, mlp_w2, mlp_b2, x1,
                                                    out, ROWS, 256, 1024);
}

// round 9
// speedup vs baseline: 1.8633x; 1.2683x over previous
#include <cuda_runtime.h>
#include <cuda_bf16.h>
#include <math.h>

// Shapes
#define BB 16
#define NN 256
#define DD 256
#define HH 8
#define HD 32
#define PD 4
#define RATIO 4
#define ROWS (BB*NN)            // 4096
#define PAIR_ROWS (BB*NN*NN)    // 1048576

// ---------------- scratch (device globals, no allocation) ----------------
__device__ float g_xn [ROWS*DD];        // 4 MB
__device__ float g_qkv[ROWS*3*DD];      // 12 MB
__device__ float g_biasT[BB*HH*NN*NN];  // 33.5 MB  [B,H,N,N]
__device__ float g_xa [ROWS*DD];        // 4 MB  [B,N,H*HD]
__device__ float g_x1 [ROWS*DD];        // 4 MB
__device__ float g_m1 [ROWS*RATIO*DD];  // 16 MB

__device__ __forceinline__ float gelu_exact(float x) {
    return 0.5f * x * (1.0f + erff(x * 0.70710678118654752f));
}

__device__ __forceinline__ unsigned f2tf32(float x) {
    unsigned r;
    asm("cvt.rna.tf32.f32 %0, %1;" : "=r"(r) : "f"(x));
    return r;
}

__device__ __forceinline__ void mma_tf32(
    float& c0, float& c1, float& c2, float& c3,
    unsigned a0, unsigned a1, unsigned a2, unsigned a3,
    unsigned b0, unsigned b1)
{
    asm volatile(
        "mma.sync.aligned.m16n8k8.row.col.f32.tf32.tf32.f32 "
        "{%0,%1,%2,%3}, {%4,%5,%6,%7}, {%8,%9}, {%0,%1,%2,%3};"
        : "+f"(c0), "+f"(c1), "+f"(c2), "+f"(c3)
        : "r"(a0), "r"(a1), "r"(a2), "r"(a3), "r"(b0), "r"(b1));
}

// ---------------- pairwise MLP (tf32 tensor cores) ----------------
#define H1S 68   // smem row stride for h1 (conflict-free fragment loads)
__global__ __launch_bounds__(256) void pairwise_kernel(
    const float* __restrict__ u,
    const float* __restrict__ w1, const float* __restrict__ b1,
    const float* __restrict__ w2, const float* __restrict__ b2,
    const float* __restrict__ w3, const float* __restrict__ b3,
    float* __restrict__ biasOut)
{
    extern __shared__ float dsm[];
    unsigned* h1s = (unsigned*)dsm;                 // 128*68
    unsigned* w2f = h1s + 128*H1S;                  // 4096 (fragment layout)
    float*    w3s = (float*)(w2f + 4096);           // 512
    float*    b2s = w3s + 512;                      // 64
    float*    b3s = b2s + 64;                       // 8
    float*    w1s = b3s + 8;                        // 256
    float*    b1s = w1s + 256;                      // 64

    int tid = threadIdx.x;
    int lane = tid & 31, warp = tid >> 5;
    int tig = lane & 3, gid = lane >> 2;

    if (tid < 64)  b1s[tid] = b1[tid];
    if (tid < 64)  b2s[tid] = b2[tid];
    if (tid < 8)   b3s[tid] = b3[tid];
    w1s[tid] = w1[tid];
    for (int i = tid; i < 512; i += 256) w3s[i] = w3[i];
    for (int idx = tid; idx < 4096; idx += 256) {
        int tile = idx >> 6;          // kt*8 + nt
        int pos  = idx & 63;
        int l    = pos >> 1, which = pos & 1;
        int kt = tile >> 3, nt = tile & 7;
        int ltig = l & 3, lgid = l >> 2;
        int k = kt*8 + ltig + which*4;
        int n = nt*8 + lgid;
        w2f[tile*64 + l*2 + which] = f2tf32(w2[k*64 + n]);
    }

    {
        int row = tid >> 1;                 // 0..127
        int c0  = (tid & 1) * 32;
        long gr = (long)blockIdx.x * 128 + row;
        float4 uv = ((const float4*)u)[gr];
        unsigned* dst = h1s + row*H1S + c0;
#pragma unroll
        for (int cc = 0; cc < 32; cc += 4) {
            unsigned pk[4];
#pragma unroll
            for (int q = 0; q < 4; q++) {
                int c = c0 + cc + q;
                float t = b1s[c] + uv.x*w1s[c] + uv.y*w1s[64+c]
                                 + uv.z*w1s[128+c] + uv.w*w1s[192+c];
                pk[q] = f2tf32(gelu_exact(t));
            }
            *(uint4*)&dst[cc] = make_uint4(pk[0], pk[1], pk[2], pk[3]);
        }
    }
    __syncthreads();

    float c[8][4];
#pragma unroll
    for (int nt = 0; nt < 8; nt++)
#pragma unroll
        for (int q = 0; q < 4; q++) c[nt][q] = 0.f;

    const unsigned* h1w = h1s + (warp*16 + gid)*H1S;
#pragma unroll
    for (int kt = 0; kt < 8; kt++) {
        unsigned a0 = h1w[kt*8 + tig];
        unsigned a1 = h1w[8*H1S + kt*8 + tig];
        unsigned a2 = h1w[kt*8 + tig + 4];
        unsigned a3 = h1w[8*H1S + kt*8 + tig + 4];
        const uint2* bf = (const uint2*)(w2f + kt*8*64);
#pragma unroll
        for (int nt = 0; nt < 8; nt++) {
            uint2 b = bf[nt*32 + lane];
            mma_tf32(c[nt][0], c[nt][1], c[nt][2], c[nt][3],
                     a0, a1, a2, a3, b.x, b.y);
        }
    }

    float acc0[8], acc1[8];
#pragma unroll
    for (int h = 0; h < 8; h++) { acc0[h] = 0.f; acc1[h] = 0.f; }

#pragma unroll
    for (int nt = 0; nt < 8; nt++) {
        int col0 = nt*8 + tig*2;
        float g00 = gelu_exact(c[nt][0] + b2s[col0]);
        float g01 = gelu_exact(c[nt][1] + b2s[col0+1]);
        float g10 = gelu_exact(c[nt][2] + b2s[col0]);
        float g11 = gelu_exact(c[nt][3] + b2s[col0+1]);
        const float4* w3r = (const float4*)&w3s[col0*8];
        float4 wa0 = w3r[0], wa1 = w3r[1];
        float4 wb0 = w3r[2], wb1 = w3r[3];
        acc0[0] += g00*wa0.x + g01*wb0.x;  acc1[0] += g10*wa0.x + g11*wb0.x;
        acc0[1] += g00*wa0.y + g01*wb0.y;  acc1[1] += g10*wa0.y + g11*wb0.y;
        acc0[2] += g00*wa0.z + g01*wb0.z;  acc1[2] += g10*wa0.z + g11*wb0.z;
        acc0[3] += g00*wa0.w + g01*wb0.w;  acc1[3] += g10*wa0.w + g11*wb0.w;
        acc0[4] += g00*wa1.x + g01*wb1.x;  acc1[4] += g10*wa1.x + g11*wb1.x;
        acc0[5] += g00*wa1.y + g01*wb1.y;  acc1[5] += g10*wa1.y + g11*wb1.y;
        acc0[6] += g00*wa1.z + g01*wb1.z;  acc1[6] += g10*wa1.z + g11*wb1.z;
        acc0[7] += g00*wa1.w + g01*wb1.w;  acc1[7] += g10*wa1.w + g11*wb1.w;
    }

#pragma unroll
    for (int h = 0; h < 8; h++) {
        acc0[h] += __shfl_xor_sync(0xffffffffu, acc0[h], 1);
        acc1[h] += __shfl_xor_sync(0xffffffffu, acc1[h], 1);
    }
#pragma unroll
    for (int h = 0; h < 8; h++) {
        acc0[h] += __shfl_xor_sync(0xffffffffu, acc0[h], 2);
        acc1[h] += __shfl_xor_sync(0xffffffffu, acc1[h], 2);
    }

    long R0 = (long)blockIdx.x * 128 + warp*16 + gid;
    int b = (int)(R0 >> 16);
    int i = (int)((R0 >> 8) & 255);
    int j0 = (int)(R0 & 255);
    int hA = tig*2, hB = hA + 1;

    float oA0 = gelu_exact(acc0[hA] + b3s[hA]);
    float oB0 = gelu_exact(acc0[hB] + b3s[hB]);
    float oA1 = gelu_exact(acc1[hA] + b3s[hA]);
    float oB1 = gelu_exact(acc1[hB] + b3s[hB]);

    long baseA = ((long)(b*8 + hA) << 16) + (i << 8);
    long baseB = ((long)(b*8 + hB) << 16) + (i << 8);
    biasOut[baseA + j0]     = oA0;
    biasOut[baseB + j0]     = oB0;
    biasOut[baseA + j0 + 8] = oA1;
    biasOut[baseB + j0 + 8] = oB1;
}

// ---------------- LayerNorm ----------------
__global__ __launch_bounds__(256) void ln_kernel(
    const float* __restrict__ x, const float* __restrict__ g,
    const float* __restrict__ bb, float* __restrict__ out)
{
    __shared__ float red[16];
    int r = blockIdx.x, t = threadIdx.x;
    float v = x[r*256 + t];

    float s = v;
#pragma unroll
    for (int o = 16; o > 0; o >>= 1) s += __shfl_xor_sync(0xffffffffu, s, o);
    if ((t & 31) == 0) red[t >> 5] = s;
    __syncthreads();
    float mu = 0.f;
#pragma unroll
    for (int w = 0; w < 8; w++) mu += red[w];
    mu *= (1.0f/256.0f);

    float d = v - mu;
    float q = d*d;
#pragma unroll
    for (int o = 16; o > 0; o >>= 1) q += __shfl_xor_sync(0xffffffffu, q, o);
    if ((t & 31) == 0) red[8 + (t >> 5)] = q;
    __syncthreads();
    float var = 0.f;
#pragma unroll
    for (int w = 0; w < 8; w++) var += red[8 + w];
    var *= (1.0f/256.0f);

    out[r*256 + t] = d * rsqrtf(var + 1e-5f) * g[t] + bb[t];
}

// ---------------- tf32 tensor-core GEMM ----------------
// C[M,N] = epi(A[M,K] @ B[K,N] + bias, res)
// Block 256 thr (8 warps, 4x2), tile 128x64, K-step 32, warp tile 32x32.
// EPI: 0 = +bias ; 1 = gelu(+bias) ; 2 = +bias +res ; 3 = gelu(+bias)+res
#define AS_STRIDE 36
#define BS_STRIDE 72
template<int EPI>
__global__ __launch_bounds__(256, 2) void tgemm_kernel(
    const float* __restrict__ A, const float* __restrict__ Bm,
    const float* __restrict__ bias, const float* __restrict__ res,
    float* __restrict__ C, int M, int Nn, int K)
{
    __shared__ unsigned As[128*AS_STRIDE];   // 18 KB
    __shared__ unsigned Bs[32*BS_STRIDE];    // 9 KB

    int tid = threadIdx.x;
    int lane = tid & 31, warp = tid >> 5;
    int tig = lane & 3, gid = lane >> 2;
    int warp_m = warp & 3, warp_n = warp >> 2;

    int row0 = blockIdx.y * 128;
    int col0 = blockIdx.x * 64;

    // staging maps
    int ar = tid >> 1;                 // 0..127
    int ac = (tid & 1) * 16;           // 0 or 16
    int br = tid >> 3;                 // 0..31
    int bc = (tid & 7) * 8;            // 0..56

    const float* Ap = A + (long)(row0 + ar)*K + ac;
    const float* Bp = Bm + (long)br*Nn + col0 + bc;

    float c[2][4][4];
#pragma unroll
    for (int mt = 0; mt < 2; mt++)
#pragma unroll
        for (int nt = 0; nt < 4; nt++)
#pragma unroll
            for (int q = 0; q < 4; q++) c[mt][nt][q] = 0.f;

    // prefetch first slab into registers
    float4 apre[4], bpre[2];
#pragma unroll
    for (int i = 0; i < 4; i++) apre[i] = *(const float4*)(Ap + 4*i);
#pragma unroll
    for (int i = 0; i < 2; i++) bpre[i] = *(const float4*)(Bp + 4*i);

    for (int k0 = 0; k0 < K; k0 += 32) {
        // store prefetched slab (tf32) to smem
        unsigned* ad = As + ar*AS_STRIDE + ac;
#pragma unroll
        for (int i = 0; i < 4; i++) {
            float4 v = apre[i];
            *(uint4*)(ad + 4*i) = make_uint4(f2tf32(v.x), f2tf32(v.y),
                                             f2tf32(v.z), f2tf32(v.w));
        }
        unsigned* bd = Bs + br*BS_STRIDE + bc;
#pragma unroll
        for (int i = 0; i < 2; i++) {
            float4 v = bpre[i];
            *(uint4*)(bd + 4*i) = make_uint4(f2tf32(v.x), f2tf32(v.y),
                                             f2tf32(v.z), f2tf32(v.w));
        }
        __syncthreads();

        // prefetch next slab
        if (k0 + 32 < K) {
#pragma unroll
            for (int i = 0; i < 4; i++) apre[i] = *(const float4*)(Ap + k0 + 32 + 4*i);
#pragma unroll
            for (int i = 0; i < 2; i++) bpre[i] = *(const float4*)(Bp + (long)(k0 + 32)*Nn + 4*i);
        }

        // compute
        const unsigned* aw0 = As + (warp_m*32 + gid)*AS_STRIDE;
        const unsigned* bw  = Bs + warp_n*32 + gid;
#pragma unroll
        for (int kt = 0; kt < 4; kt++) {
            unsigned af[2][4];
#pragma unroll
            for (int mt = 0; mt < 2; mt++) {
                const unsigned* aw = aw0 + mt*16*AS_STRIDE + kt*8;
                af[mt][0] = aw[tig];
                af[mt][1] = aw[8*AS_STRIDE + tig];
                af[mt][2] = aw[tig + 4];
                af[mt][3] = aw[8*AS_STRIDE + tig + 4];
            }
#pragma unroll
            for (int nt = 0; nt < 4; nt++) {
                const unsigned* bww = bw + (kt*8 + tig)*BS_STRIDE + nt*8;
                unsigned b0 = bww[0];
                unsigned b1 = bww[4*BS_STRIDE];
#pragma unroll
                for (int mt = 0; mt < 2; mt++)
                    mma_tf32(c[mt][nt][0], c[mt][nt][1], c[mt][nt][2], c[mt][nt][3],
                             af[mt][0], af[mt][1], af[mt][2], af[mt][3], b0, b1);
            }
        }
        __syncthreads();
    }

    // epilogue
#pragma unroll
    for (int mt = 0; mt < 2; mt++) {
#pragma unroll
        for (int half = 0; half < 2; half++) {
            int r = row0 + warp_m*32 + mt*16 + gid + half*8;
#pragma unroll
            for (int nt = 0; nt < 4; nt++) {
                int cc = col0 + warp_n*32 + nt*8 + tig*2;
                float v0 = c[mt][nt][half*2 + 0] + bias[cc];
                float v1 = c[mt][nt][half*2 + 1] + bias[cc + 1];
                if (EPI == 1 || EPI == 3) { v0 = gelu_exact(v0); v1 = gelu_exact(v1); }
                if (EPI == 2 || EPI == 3) {
                    const float2 rr = *(const float2*)&res[(long)r*Nn + cc];
                    v0 += rr.x; v1 += rr.y;
                }
                *(float2*)&C[(long)r*Nn + cc] = make_float2(v0, v1);
            }
        }
    }
}

// ---------------- Fused attention: warp-autonomous, one block per (b,h) ---
#define KVSTRIDE 36
__global__ __launch_bounds__(512) void attn_kernel(
    const float* __restrict__ qkv, const float* __restrict__ biasT,
    const unsigned char* __restrict__ mask, float* __restrict__ xa)
{
    extern __shared__ float sm[];
    float* Ks = sm;                        // 256*36
    float* Vs = Ks + 256*KVSTRIDE;         // 256*36
    float* Ps = Vs + 256*KVSTRIDE;         // 16*512

    int tid  = threadIdx.x;
    int warp = tid >> 5, lane = tid & 31;
    int bh = blockIdx.x;
    int b = bh >> 3, h = bh & 7;

    const float* base = qkv + (long)b*256*768 + h*32;

    for (int idx = tid; idx < 2048; idx += 512) {
        int row = idx >> 3, d4 = (idx & 7) << 2;
        const float* src = base + (long)row*768;
        *(float4*)&Ks[row*KVSTRIDE + d4] = *(const float4*)(src + 256 + d4);
        *(float4*)&Vs[row*KVSTRIDE + d4] = *(const float4*)(src + 512 + d4);
    }
    __syncthreads();

    unsigned mk = 0;
#pragma unroll
    for (int c = 0; c < 8; c++)
        if (mask[b*256 + c*32 + lane]) mk |= (1u << c);

    float* p0 = Ps + warp*512;
    float* p1 = p0 + 256;
    const float scale = 0.17677669529663687f;   // 1/sqrt(32)

    for (int ii = 0; ii < 16; ii += 2) {
        int i0 = warp*16 + ii, i1 = i0 + 1;

        float q0[32], q1[32];
        const float* q0p = base + (long)i0*768;
        const float* q1p = base + (long)i1*768;
#pragma unroll
        for (int d4 = 0; d4 < 8; d4++) {
            float4 t0 = *(const float4*)(q0p + 4*d4);
            q0[4*d4]=t0.x; q0[4*d4+1]=t0.y; q0[4*d4+2]=t0.z; q0[4*d4+3]=t0.w;
            float4 t1 = *(const float4*)(q1p + 4*d4);
            q1[4*d4]=t1.x; q1[4*d4+1]=t1.y; q1[4*d4+2]=t1.z; q1[4*d4+3]=t1.w;
        }

        const float* br0 = biasT + ((long)(bh*256 + i0) << 8);
        const float* br1 = biasT + ((long)(bh*256 + i1) << 8);
        float s0[8], s1[8];
#pragma unroll
        for (int c = 0; c < 8; c++) {
            s0[c] = br0[c*32 + lane];
            s1[c] = br1[c*32 + lane];
        }

#pragma unroll
        for (int c = 0; c < 8; c++) {
            const float4* kr = (const float4*)&Ks[(c*32 + lane)*KVSTRIDE];
            float a0 = 0.f, a1 = 0.f;
#pragma unroll
            for (int d4 = 0; d4 < 8; d4++) {
                float4 k4 = kr[d4];
                a0 += q0[4*d4]*k4.x + q0[4*d4+1]*k4.y + q0[4*d4+2]*k4.z + q0[4*d4+3]*k4.w;
                a1 += q1[4*d4]*k4.x + q1[4*d4+1]*k4.y + q1[4*d4+2]*k4.z + q1[4*d4+3]*k4.w;
            }
            s0[c] += a0 * scale;
            s1[c] += a1 * scale;
            if ((mk >> c) & 1) { s0[c] = -1e30f; s1[c] = -1e30f; }
        }

        float m0 = s0[0], m1 = s1[0];
#pragma unroll
        for (int c = 1; c < 8; c++) { m0 = fmaxf(m0, s0[c]); m1 = fmaxf(m1, s1[c]); }
#pragma unroll
        for (int o = 16; o > 0; o >>= 1) {
            m0 = fmaxf(m0, __shfl_xor_sync(0xffffffffu, m0, o));
            m1 = fmaxf(m1, __shfl_xor_sync(0xffffffffu, m1, o));
        }
        float z0 = 0.f, z1 = 0.f;
#pragma unroll
        for (int c = 0; c < 8; c++) {
            s0[c] = __expf(s0[c] - m0);  z0 += s0[c];
            s1[c] = __expf(s1[c] - m1);  z1 += s1[c];
        }
#pragma unroll
        for (int o = 16; o > 0; o >>= 1) {
            z0 += __shfl_xor_sync(0xffffffffu, z0, o);
            z1 += __shfl_xor_sync(0xffffffffu, z1, o);
        }
        float rz0 = 1.0f / z0, rz1 = 1.0f / z1;

#pragma unroll
        for (int c = 0; c < 8; c++) { p0[c*32 + lane] = s0[c]; p1[c*32 + lane] = s1[c]; }
        __syncwarp();

        float acc0 = 0.f, acc1 = 0.f;
        const float4* p04 = (const float4*)p0;
        const float4* p14 = (const float4*)p1;
#pragma unroll
        for (int c = 0; c < 8; c++) {
#pragma unroll
            for (int j4 = 0; j4 < 8; j4++) {
                float4 P0 = p04[c*8 + j4];
                float4 P1 = p14[c*8 + j4];
                int j = c*32 + j4*4;
                float v0 = Vs[(j+0)*KVSTRIDE + lane];
                float v1 = Vs[(j+1)*KVSTRIDE + lane];
                float v2 = Vs[(j+2)*KVSTRIDE + lane];
                float v3 = Vs[(j+3)*KVSTRIDE + lane];
                acc0 += P0.x*v0 + P0.y*v1 + P0.z*v2 + P0.w*v3;
                acc1 += P1.x*v0 + P1.y*v1 + P1.z*v2 + P1.w*v3;
            }
        }
        __syncwarp();

        xa[(long)(b*256 + i0)*256 + h*32 + lane] = acc0 * rz0;
        xa[(long)(b*256 + i1)*256 + h*32 + lane] = acc1 * rz1;
    }
}

// ---------------- launch ----------------
extern "C" void kernel_launch(void* const* d_in, const int* in_sizes, int n_in,
                              void* d_out, int out_size)
{
    const float* x      = (const float*)d_in[0];
    const float* u      = (const float*)d_in[1];
    const unsigned char* mask = (const unsigned char*)d_in[2];
    const float* n1_g   = (const float*)d_in[3];
    const float* n1_b   = (const float*)d_in[4];
    const float* qkv_w  = (const float*)d_in[5];
    const float* qkv_b  = (const float*)d_in[6];
    const float* proj_w = (const float*)d_in[7];
    const float* proj_b = (const float*)d_in[8];
    const float* n2_g   = (const float*)d_in[9];
    const float* n2_b   = (const float*)d_in[10];
    const float* mlp_w1 = (const float*)d_in[11];
    const float* mlp_b1 = (const float*)d_in[12];
    const float* mlp_w2 = (const float*)d_in[13];
    const float* mlp_b2 = (const float*)d_in[14];
    const float* pw_w1  = (const float*)d_in[15];
    const float* pw_b1  = (const float*)d_in[16];
    const float* pw_w2  = (const float*)d_in[17];
    const float* pw_b2  = (const float*)d_in[18];
    const float* pw_w3  = (const float*)d_in[19];
    const float* pw_b3  = (const float*)d_in[20];
    float* out = (float*)d_out;

    float *xn, *qkvb, *biasT, *xa, *x1, *m1;
    cudaGetSymbolAddress((void**)&xn,    g_xn);
    cudaGetSymbolAddress((void**)&qkvb,  g_qkv);
    cudaGetSymbolAddress((void**)&biasT, g_biasT);
    cudaGetSymbolAddress((void**)&xa,    g_xa);
    cudaGetSymbolAddress((void**)&x1,    g_x1);
    cudaGetSymbolAddress((void**)&m1,    g_m1);

    // 1. pairwise MLP (tf32 mma) -> bias[B,H,N,N]
    int pw_smem = (128*H1S + 4096 + 512 + 64 + 8 + 256 + 64) * 4;
    cudaFuncSetAttribute(pairwise_kernel,
                         cudaFuncAttributeMaxDynamicSharedMemorySize, pw_smem);
    pairwise_kernel<<<PAIR_ROWS/128, 256, pw_smem>>>(u, pw_w1, pw_b1, pw_w2, pw_b2,
                                                     pw_w3, pw_b3, biasT);
    // 2. LN1
    ln_kernel<<<ROWS, 256>>>(x, n1_g, n1_b, xn);
    // 3. QKV GEMM (tf32)  [4096,256] x [256,768]
    tgemm_kernel<0><<<dim3(768/64, ROWS/128), 256>>>(xn, qkv_w, qkv_b, nullptr,
                                                     qkvb, ROWS, 768, 256);
    // 4. attention
    int attn_smem = (256*KVSTRIDE*2 + 16*512) * sizeof(float);
    cudaFuncSetAttribute(attn_kernel, cudaFuncAttributeMaxDynamicSharedMemorySize,
                         attn_smem);
    attn_kernel<<<BB*HH, 512, attn_smem>>>(qkvb, biasT, mask, xa);
    // 5. proj + residual -> x1  (tf32)
    tgemm_kernel<2><<<dim3(256/64, ROWS/128), 256>>>(xa, proj_w, proj_b, x,
                                                     x1, ROWS, 256, 256);
    // 6. LN2
    ln_kernel<<<ROWS, 256>>>(x1, n2_g, n2_b, xn);
    // 7. MLP1 + gelu (tf32)
    tgemm_kernel<1><<<dim3(1024/64, ROWS/128), 256>>>(xn, mlp_w1, mlp_b1, nullptr,
                                                      m1, ROWS, 1024, 256);
    // 8. MLP2 + gelu + residual -> out (tf32)
    tgemm_kernel<3><<<dim3(256/64, ROWS/128), 256>>>(m1, mlp_w2, mlp_b2, x1,
                                                     out, ROWS, 256, 1024);
}

// round 10
// speedup vs baseline: 1.8836x; 1.0109x over previous
#include <cuda_runtime.h>
#include <cuda_bf16.h>
#include <math.h>

// Shapes
#define BB 16
#define NN 256
#define DD 256
#define HH 8
#define HD 32
#define PD 4
#define RATIO 4
#define ROWS (BB*NN)            // 4096
#define PAIR_ROWS (BB*NN*NN)    // 1048576

// ---------------- scratch (device globals, no allocation) ----------------
__device__ float g_xn [ROWS*DD];        // 4 MB
__device__ float g_qkv[ROWS*3*DD];      // 12 MB
__device__ float g_biasT[BB*HH*NN*NN];  // 33.5 MB  [B,H,N,N]
__device__ float g_xa [ROWS*DD];        // 4 MB  [B,N,H*HD]
__device__ float g_x1 [ROWS*DD];        // 4 MB
__device__ float g_m1 [ROWS*RATIO*DD];  // 16 MB

__device__ __forceinline__ float gelu_exact(float x) {
    return 0.5f * x * (1.0f + erff(x * 0.70710678118654752f));
}

__device__ __forceinline__ unsigned f2tf32(float x) {
    unsigned r;
    asm("cvt.rna.tf32.f32 %0, %1;" : "=r"(r) : "f"(x));
    return r;
}

__device__ __forceinline__ void mma_tf32(
    float& c0, float& c1, float& c2, float& c3,
    unsigned a0, unsigned a1, unsigned a2, unsigned a3,
    unsigned b0, unsigned b1)
{
    asm volatile(
        "mma.sync.aligned.m16n8k8.row.col.f32.tf32.tf32.f32 "
        "{%0,%1,%2,%3}, {%4,%5,%6,%7}, {%8,%9}, {%0,%1,%2,%3};"
        : "+f"(c0), "+f"(c1), "+f"(c2), "+f"(c3)
        : "r"(a0), "r"(a1), "r"(a2), "r"(a3), "r"(b0), "r"(b1));
}

__device__ __forceinline__ unsigned sptr(const void* p) {
    return (unsigned)__cvta_generic_to_shared(p);
}
__device__ __forceinline__ void cp16(unsigned s, const float* g) {
    asm volatile("cp.async.cg.shared.global [%0], [%1], 16;" :: "r"(s), "l"(g));
}

// ---------------- pairwise MLP (tf32 tensor cores) ----------------
#define H1S 68   // smem row stride for h1 (conflict-free fragment loads)
__global__ __launch_bounds__(256) void pairwise_kernel(
    const float* __restrict__ u,
    const float* __restrict__ w1, const float* __restrict__ b1,
    const float* __restrict__ w2, const float* __restrict__ b2,
    const float* __restrict__ w3, const float* __restrict__ b3,
    float* __restrict__ biasOut)
{
    extern __shared__ float dsm[];
    unsigned* h1s = (unsigned*)dsm;                 // 128*68
    unsigned* w2f = h1s + 128*H1S;                  // 4096 (fragment layout)
    float*    w3s = (float*)(w2f + 4096);           // 512
    float*    b2s = w3s + 512;                      // 64
    float*    b3s = b2s + 64;                       // 8
    float*    w1s = b3s + 8;                        // 256
    float*    b1s = w1s + 256;                      // 64

    int tid = threadIdx.x;
    int lane = tid & 31, warp = tid >> 5;
    int tig = lane & 3, gid = lane >> 2;

    if (tid < 64)  b1s[tid] = b1[tid];
    if (tid < 64)  b2s[tid] = b2[tid];
    if (tid < 8)   b3s[tid] = b3[tid];
    w1s[tid] = w1[tid];
    for (int i = tid; i < 512; i += 256) w3s[i] = w3[i];
    for (int idx = tid; idx < 4096; idx += 256) {
        int tile = idx >> 6;          // kt*8 + nt
        int pos  = idx & 63;
        int l    = pos >> 1, which = pos & 1;
        int kt = tile >> 3, nt = tile & 7;
        int ltig = l & 3, lgid = l >> 2;
        int k = kt*8 + ltig + which*4;
        int n = nt*8 + lgid;
        w2f[tile*64 + l*2 + which] = f2tf32(w2[k*64 + n]);
    }

    {
        int row = tid >> 1;                 // 0..127
        int c0  = (tid & 1) * 32;
        long gr = (long)blockIdx.x * 128 + row;
        float4 uv = ((const float4*)u)[gr];
        unsigned* dst = h1s + row*H1S + c0;
#pragma unroll
        for (int cc = 0; cc < 32; cc += 4) {
            unsigned pk[4];
#pragma unroll
            for (int q = 0; q < 4; q++) {
                int c = c0 + cc + q;
                float t = b1s[c] + uv.x*w1s[c] + uv.y*w1s[64+c]
                                 + uv.z*w1s[128+c] + uv.w*w1s[192+c];
                pk[q] = f2tf32(gelu_exact(t));
            }
            *(uint4*)&dst[cc] = make_uint4(pk[0], pk[1], pk[2], pk[3]);
        }
    }
    __syncthreads();

    float c[8][4];
#pragma unroll
    for (int nt = 0; nt < 8; nt++)
#pragma unroll
        for (int q = 0; q < 4; q++) c[nt][q] = 0.f;

    const unsigned* h1w = h1s + (warp*16 + gid)*H1S;
#pragma unroll
    for (int kt = 0; kt < 8; kt++) {
        unsigned a0 = h1w[kt*8 + tig];
        unsigned a1 = h1w[8*H1S + kt*8 + tig];
        unsigned a2 = h1w[kt*8 + tig + 4];
        unsigned a3 = h1w[8*H1S + kt*8 + tig + 4];
        const uint2* bf = (const uint2*)(w2f + kt*8*64);
#pragma unroll
        for (int nt = 0; nt < 8; nt++) {
            uint2 b = bf[nt*32 + lane];
            mma_tf32(c[nt][0], c[nt][1], c[nt][2], c[nt][3],
                     a0, a1, a2, a3, b.x, b.y);
        }
    }

    float acc0[8], acc1[8];
#pragma unroll
    for (int h = 0; h < 8; h++) { acc0[h] = 0.f; acc1[h] = 0.f; }

#pragma unroll
    for (int nt = 0; nt < 8; nt++) {
        int col0 = nt*8 + tig*2;
        float g00 = gelu_exact(c[nt][0] + b2s[col0]);
        float g01 = gelu_exact(c[nt][1] + b2s[col0+1]);
        float g10 = gelu_exact(c[nt][2] + b2s[col0]);
        float g11 = gelu_exact(c[nt][3] + b2s[col0+1]);
        const float4* w3r = (const float4*)&w3s[col0*8];
        float4 wa0 = w3r[0], wa1 = w3r[1];
        float4 wb0 = w3r[2], wb1 = w3r[3];
        acc0[0] += g00*wa0.x + g01*wb0.x;  acc1[0] += g10*wa0.x + g11*wb0.x;
        acc0[1] += g00*wa0.y + g01*wb0.y;  acc1[1] += g10*wa0.y + g11*wb0.y;
        acc0[2] += g00*wa0.z + g01*wb0.z;  acc1[2] += g10*wa0.z + g11*wb0.z;
        acc0[3] += g00*wa0.w + g01*wb0.w;  acc1[3] += g10*wa0.w + g11*wb0.w;
        acc0[4] += g00*wa1.x + g01*wb1.x;  acc1[4] += g10*wa1.x + g11*wb1.x;
        acc0[5] += g00*wa1.y + g01*wb1.y;  acc1[5] += g10*wa1.y + g11*wb1.y;
        acc0[6] += g00*wa1.z + g01*wb1.z;  acc1[6] += g10*wa1.z + g11*wb1.z;
        acc0[7] += g00*wa1.w + g01*wb1.w;  acc1[7] += g10*wa1.w + g11*wb1.w;
    }

#pragma unroll
    for (int h = 0; h < 8; h++) {
        acc0[h] += __shfl_xor_sync(0xffffffffu, acc0[h], 1);
        acc1[h] += __shfl_xor_sync(0xffffffffu, acc1[h], 1);
    }
#pragma unroll
    for (int h = 0; h < 8; h++) {
        acc0[h] += __shfl_xor_sync(0xffffffffu, acc0[h], 2);
        acc1[h] += __shfl_xor_sync(0xffffffffu, acc1[h], 2);
    }

    long R0 = (long)blockIdx.x * 128 + warp*16 + gid;
    int b = (int)(R0 >> 16);
    int i = (int)((R0 >> 8) & 255);
    int j0 = (int)(R0 & 255);
    int hA = tig*2, hB = hA + 1;

    float oA0 = gelu_exact(acc0[hA] + b3s[hA]);
    float oB0 = gelu_exact(acc0[hB] + b3s[hB]);
    float oA1 = gelu_exact(acc1[hA] + b3s[hA]);
    float oB1 = gelu_exact(acc1[hB] + b3s[hB]);

    long baseA = ((long)(b*8 + hA) << 16) + (i << 8);
    long baseB = ((long)(b*8 + hB) << 16) + (i << 8);
    biasOut[baseA + j0]     = oA0;
    biasOut[baseB + j0]     = oB0;
    biasOut[baseA + j0 + 8] = oA1;
    biasOut[baseB + j0 + 8] = oB1;
}

// ---------------- LayerNorm ----------------
__global__ __launch_bounds__(256) void ln_kernel(
    const float* __restrict__ x, const float* __restrict__ g,
    const float* __restrict__ bb, float* __restrict__ out)
{
    __shared__ float red[16];
    int r = blockIdx.x, t = threadIdx.x;
    float v = x[r*256 + t];

    float s = v;
#pragma unroll
    for (int o = 16; o > 0; o >>= 1) s += __shfl_xor_sync(0xffffffffu, s, o);
    if ((t & 31) == 0) red[t >> 5] = s;
    __syncthreads();
    float mu = 0.f;
#pragma unroll
    for (int w = 0; w < 8; w++) mu += red[w];
    mu *= (1.0f/256.0f);

    float d = v - mu;
    float q = d*d;
#pragma unroll
    for (int o = 16; o > 0; o >>= 1) q += __shfl_xor_sync(0xffffffffu, q, o);
    if ((t & 31) == 0) red[8 + (t >> 5)] = q;
    __syncthreads();
    float var = 0.f;
#pragma unroll
    for (int w = 0; w < 8; w++) var += red[8 + w];
    var *= (1.0f/256.0f);

    out[r*256 + t] = d * rsqrtf(var + 1e-5f) * g[t] + bb[t];
}

// ---------------- tf32 tensor-core GEMM v3 (cp.async double-buffered) -------
// C[M,N] = epi(A[M,K] @ B[K,N] + bias, res)
// Block 256 thr (8 warps, 4x2), tile 128x64, K-step 32, warp tile 32x32.
// EPI: 0 = +bias ; 1 = gelu(+bias) ; 2 = +bias +res ; 3 = gelu(+bias)+res
#define AS_STRIDE 36
#define BS_STRIDE 72
#define A_BUF (128*AS_STRIDE)
#define B_BUF (32*BS_STRIDE)
#define TG_SMEM ((2*A_BUF + 2*B_BUF)*4)
template<int EPI>
__global__ __launch_bounds__(256, 2) void tgemm_kernel(
    const float* __restrict__ A, const float* __restrict__ Bm,
    const float* __restrict__ bias, const float* __restrict__ res,
    float* __restrict__ C, int M, int Nn, int K)
{
    extern __shared__ float tsm[];
    float* As = tsm;                 // 2 bufs of 128*36
    float* Bs = tsm + 2*A_BUF;       // 2 bufs of 32*72

    int tid = threadIdx.x;
    int lane = tid & 31, warp = tid >> 5;
    int tig = lane & 3, gid = lane >> 2;
    int warp_m = warp & 3, warp_n = warp >> 2;

    int row0 = blockIdx.y * 128;
    int col0 = blockIdx.x * 64;

    // copy maps: A thread copies 16 floats of one row; B copies 8 floats.
    int ar = tid >> 1, ac = (tid & 1) * 16;
    int br = tid >> 3, bc = (tid & 7) * 8;

    const float* Ap = A + (long)(row0 + ar)*K + ac;
    const float* Bp = Bm + (long)br*Nn + col0 + bc;

    unsigned a_sb = sptr(&As[ar*AS_STRIDE + ac]);
    unsigned b_sb = sptr(&Bs[br*BS_STRIDE + bc]);

    float c[2][4][4];
#pragma unroll
    for (int mt = 0; mt < 2; mt++)
#pragma unroll
        for (int nt = 0; nt < 4; nt++)
#pragma unroll
            for (int q = 0; q < 4; q++) c[mt][nt][q] = 0.f;

    int iters = K >> 5;

    // prologue: issue slab 0 into buf 0
    {
        const float* ag = Ap;
#pragma unroll
        for (int i = 0; i < 4; i++) cp16(a_sb + 16*i, ag + 4*i);
        const float* bg = Bp;
#pragma unroll
        for (int i = 0; i < 2; i++) cp16(b_sb + 16*i, bg + 4*i);
        asm volatile("cp.async.commit_group;");
    }

    for (int it = 0; it < iters; it++) {
        int buf = it & 1;
        if (it + 1 < iters) {
            int nbuf = buf ^ 1;
            const float* ag = Ap + (it + 1)*32;
#pragma unroll
            for (int i = 0; i < 4; i++) cp16(a_sb + nbuf*A_BUF*4 + 16*i, ag + 4*i);
            const float* bg = Bp + (long)(it + 1)*32*Nn;
#pragma unroll
            for (int i = 0; i < 2; i++) cp16(b_sb + nbuf*B_BUF*4 + 16*i, bg + 4*i);
            asm volatile("cp.async.commit_group;");
            asm volatile("cp.async.wait_group 1;");
        } else {
            asm volatile("cp.async.wait_group 0;");
        }
        __syncthreads();

        const float* aw0 = As + buf*A_BUF + (warp_m*32 + gid)*AS_STRIDE;
        const float* bw  = Bs + buf*B_BUF + warp_n*32 + gid;
#pragma unroll
        for (int kt = 0; kt < 4; kt++) {
            unsigned af[2][4];
#pragma unroll
            for (int mt = 0; mt < 2; mt++) {
                const float* aw = aw0 + mt*16*AS_STRIDE + kt*8;
                af[mt][0] = f2tf32(aw[tig]);
                af[mt][1] = f2tf32(aw[8*AS_STRIDE + tig]);
                af[mt][2] = f2tf32(aw[tig + 4]);
                af[mt][3] = f2tf32(aw[8*AS_STRIDE + tig + 4]);
            }
#pragma unroll
            for (int nt = 0; nt < 4; nt++) {
                const float* bww = bw + (kt*8 + tig)*BS_STRIDE + nt*8;
                unsigned b0 = f2tf32(bww[0]);
                unsigned b1 = f2tf32(bww[4*BS_STRIDE]);
#pragma unroll
                for (int mt = 0; mt < 2; mt++)
                    mma_tf32(c[mt][nt][0], c[mt][nt][1], c[mt][nt][2], c[mt][nt][3],
                             af[mt][0], af[mt][1], af[mt][2], af[mt][3], b0, b1);
            }
        }
        __syncthreads();
    }

    // epilogue
#pragma unroll
    for (int mt = 0; mt < 2; mt++) {
#pragma unroll
        for (int half = 0; half < 2; half++) {
            int r = row0 + warp_m*32 + mt*16 + gid + half*8;
#pragma unroll
            for (int nt = 0; nt < 4; nt++) {
                int cc = col0 + warp_n*32 + nt*8 + tig*2;
                float v0 = c[mt][nt][half*2 + 0] + bias[cc];
                float v1 = c[mt][nt][half*2 + 1] + bias[cc + 1];
                if (EPI == 1 || EPI == 3) { v0 = gelu_exact(v0); v1 = gelu_exact(v1); }
                if (EPI == 2 || EPI == 3) {
                    const float2 rr = *(const float2*)&res[(long)r*Nn + cc];
                    v0 += rr.x; v1 += rr.y;
                }
                *(float2*)&C[(long)r*Nn + cc] = make_float2(v0, v1);
            }
        }
    }
}

// ---------------- Fused attention v3: 2 blocks per (b,h), 2 blocks/SM -------
// grid = 256, block = 512 (16 warps). Each block owns 128 query rows;
// warp owns 8 rows processed in pairs. K/V staged once per block.
#define KVSTRIDE 36
#define ATTN_SMEM ((256*KVSTRIDE*2 + 16*512)*4)
__global__ __launch_bounds__(512) void attn_kernel(
    const float* __restrict__ qkv, const float* __restrict__ biasT,
    const unsigned char* __restrict__ mask, float* __restrict__ xa)
{
    extern __shared__ float sm[];
    float* Ks = sm;                        // 256*36
    float* Vs = Ks + 256*KVSTRIDE;         // 256*36
    float* Ps = Vs + 256*KVSTRIDE;         // 16*512

    int tid  = threadIdx.x;
    int warp = tid >> 5, lane = tid & 31;
    int blk = blockIdx.x;
    int bh = blk >> 1, itile = blk & 1;
    int b = bh >> 3, h = bh & 7;

    const float* base = qkv + (long)b*256*768 + h*32;

    for (int idx = tid; idx < 2048; idx += 512) {
        int row = idx >> 3, d4 = (idx & 7) << 2;
        const float* src = base + (long)row*768;
        *(float4*)&Ks[row*KVSTRIDE + d4] = *(const float4*)(src + 256 + d4);
        *(float4*)&Vs[row*KVSTRIDE + d4] = *(const float4*)(src + 512 + d4);
    }
    __syncthreads();

    unsigned mk = 0;
#pragma unroll
    for (int c = 0; c < 8; c++)
        if (mask[b*256 + c*32 + lane]) mk |= (1u << c);

    float* p0 = Ps + warp*512;
    float* p1 = p0 + 256;
    const float scale = 0.17677669529663687f;   // 1/sqrt(32)

    for (int ii = 0; ii < 8; ii += 2) {
        int i0 = itile*128 + warp*8 + ii, i1 = i0 + 1;

        float q0[32], q1[32];
        const float* q0p = base + (long)i0*768;
        const float* q1p = base + (long)i1*768;
#pragma unroll
        for (int d4 = 0; d4 < 8; d4++) {
            float4 t0 = *(const float4*)(q0p + 4*d4);
            q0[4*d4]=t0.x; q0[4*d4+1]=t0.y; q0[4*d4+2]=t0.z; q0[4*d4+3]=t0.w;
            float4 t1 = *(const float4*)(q1p + 4*d4);
            q1[4*d4]=t1.x; q1[4*d4+1]=t1.y; q1[4*d4+2]=t1.z; q1[4*d4+3]=t1.w;
        }

        const float* br0 = biasT + ((long)(bh*256 + i0) << 8);
        const float* br1 = biasT + ((long)(bh*256 + i1) << 8);
        float s0[8], s1[8];
#pragma unroll
        for (int c = 0; c < 8; c++) {
            s0[c] = br0[c*32 + lane];
            s1[c] = br1[c*32 + lane];
        }

#pragma unroll
        for (int c = 0; c < 8; c++) {
            const float4* kr = (const float4*)&Ks[(c*32 + lane)*KVSTRIDE];
            float a0 = 0.f, a1 = 0.f;
#pragma unroll
            for (int d4 = 0; d4 < 8; d4++) {
                float4 k4 = kr[d4];
                a0 += q0[4*d4]*k4.x + q0[4*d4+1]*k4.y + q0[4*d4+2]*k4.z + q0[4*d4+3]*k4.w;
                a1 += q1[4*d4]*k4.x + q1[4*d4+1]*k4.y + q1[4*d4+2]*k4.z + q1[4*d4+3]*k4.w;
            }
            s0[c] += a0 * scale;
            s1[c] += a1 * scale;
            if ((mk >> c) & 1) { s0[c] = -1e30f; s1[c] = -1e30f; }
        }

        float m0 = s0[0], m1 = s1[0];
#pragma unroll
        for (int c = 1; c < 8; c++) { m0 = fmaxf(m0, s0[c]); m1 = fmaxf(m1, s1[c]); }
#pragma unroll
        for (int o = 16; o > 0; o >>= 1) {
            m0 = fmaxf(m0, __shfl_xor_sync(0xffffffffu, m0, o));
            m1 = fmaxf(m1, __shfl_xor_sync(0xffffffffu, m1, o));
        }
        float z0 = 0.f, z1 = 0.f;
#pragma unroll
        for (int c = 0; c < 8; c++) {
            s0[c] = __expf(s0[c] - m0);  z0 += s0[c];
            s1[c] = __expf(s1[c] - m1);  z1 += s1[c];
        }
#pragma unroll
        for (int o = 16; o > 0; o >>= 1) {
            z0 += __shfl_xor_sync(0xffffffffu, z0, o);
            z1 += __shfl_xor_sync(0xffffffffu, z1, o);
        }
        float rz0 = 1.0f / z0, rz1 = 1.0f / z1;

#pragma unroll
        for (int c = 0; c < 8; c++) { p0[c*32 + lane] = s0[c]; p1[c*32 + lane] = s1[c]; }
        __syncwarp();

        float acc0 = 0.f, acc1 = 0.f;
        const float4* p04 = (const float4*)p0;
        const float4* p14 = (const float4*)p1;
#pragma unroll
        for (int c = 0; c < 8; c++) {
#pragma unroll
            for (int j4 = 0; j4 < 8; j4++) {
                float4 P0 = p04[c*8 + j4];
                float4 P1 = p14[c*8 + j4];
                int j = c*32 + j4*4;
                float v0 = Vs[(j+0)*KVSTRIDE + lane];
                float v1 = Vs[(j+1)*KVSTRIDE + lane];
                float v2 = Vs[(j+2)*KVSTRIDE + lane];
                float v3 = Vs[(j+3)*KVSTRIDE + lane];
                acc0 += P0.x*v0 + P0.y*v1 + P0.z*v2 + P0.w*v3;
                acc1 += P1.x*v0 + P1.y*v1 + P1.z*v2 + P1.w*v3;
            }
        }
        __syncwarp();

        xa[(long)(b*256 + i0)*256 + h*32 + lane] = acc0 * rz0;
        xa[(long)(b*256 + i1)*256 + h*32 + lane] = acc1 * rz1;
    }
}

// ---------------- launch ----------------
extern "C" void kernel_launch(void* const* d_in, const int* in_sizes, int n_in,
                              void* d_out, int out_size)
{
    const float* x      = (const float*)d_in[0];
    const float* u      = (const float*)d_in[1];
    const unsigned char* mask = (const unsigned char*)d_in[2];
    const float* n1_g   = (const float*)d_in[3];
    const float* n1_b   = (const float*)d_in[4];
    const float* qkv_w  = (const float*)d_in[5];
    const float* qkv_b  = (const float*)d_in[6];
    const float* proj_w = (const float*)d_in[7];
    const float* proj_b = (const float*)d_in[8];
    const float* n2_g   = (const float*)d_in[9];
    const float* n2_b   = (const float*)d_in[10];
    const float* mlp_w1 = (const float*)d_in[11];
    const float* mlp_b1 = (const float*)d_in[12];
    const float* mlp_w2 = (const float*)d_in[13];
    const float* mlp_b2 = (const float*)d_in[14];
    const float* pw_w1  = (const float*)d_in[15];
    const float* pw_b1  = (const float*)d_in[16];
    const float* pw_w2  = (const float*)d_in[17];
    const float* pw_b2  = (const float*)d_in[18];
    const float* pw_w3  = (const float*)d_in[19];
    const float* pw_b3  = (const float*)d_in[20];
    float* out = (float*)d_out;

    float *xn, *qkvb, *biasT, *xa, *x1, *m1;
    cudaGetSymbolAddress((void**)&xn,    g_xn);
    cudaGetSymbolAddress((void**)&qkvb,  g_qkv);
    cudaGetSymbolAddress((void**)&biasT, g_biasT);
    cudaGetSymbolAddress((void**)&xa,    g_xa);
    cudaGetSymbolAddress((void**)&x1,    g_x1);
    cudaGetSymbolAddress((void**)&m1,    g_m1);

    // 1. pairwise MLP (tf32 mma) -> bias[B,H,N,N]
    int pw_smem = (128*H1S + 4096 + 512 + 64 + 8 + 256 + 64) * 4;
    cudaFuncSetAttribute(pairwise_kernel,
                         cudaFuncAttributeMaxDynamicSharedMemorySize, pw_smem);
    pairwise_kernel<<<PAIR_ROWS/128, 256, pw_smem>>>(u, pw_w1, pw_b1, pw_w2, pw_b2,
                                                     pw_w3, pw_b3, biasT);
    // 2. LN1
    ln_kernel<<<ROWS, 256>>>(x, n1_g, n1_b, xn);

    // opt-in smem for all tgemm instantiations
    cudaFuncSetAttribute(tgemm_kernel<0>, cudaFuncAttributeMaxDynamicSharedMemorySize, TG_SMEM);
    cudaFuncSetAttribute(tgemm_kernel<1>, cudaFuncAttributeMaxDynamicSharedMemorySize, TG_SMEM);
    cudaFuncSetAttribute(tgemm_kernel<2>, cudaFuncAttributeMaxDynamicSharedMemorySize, TG_SMEM);
    cudaFuncSetAttribute(tgemm_kernel<3>, cudaFuncAttributeMaxDynamicSharedMemorySize, TG_SMEM);

    // 3. QKV GEMM (tf32)  [4096,256] x [256,768]
    tgemm_kernel<0><<<dim3(768/64, ROWS/128), 256, TG_SMEM>>>(xn, qkv_w, qkv_b, nullptr,
                                                              qkvb, ROWS, 768, 256);
    // 4. attention (2 blocks per head, 2 blocks/SM)
    cudaFuncSetAttribute(attn_kernel, cudaFuncAttributeMaxDynamicSharedMemorySize,
                         ATTN_SMEM);
    attn_kernel<<<BB*HH*2, 512, ATTN_SMEM>>>(qkvb, biasT, mask, xa);
    // 5. proj + residual -> x1  (tf32)
    tgemm_kernel<2><<<dim3(256/64, ROWS/128), 256, TG_SMEM>>>(xa, proj_w, proj_b, x,
                                                              x1, ROWS, 256, 256);
    // 6. LN2
    ln_kernel<<<ROWS, 256>>>(x1, n2_g, n2_b, xn);
    // 7. MLP1 + gelu (tf32)
    tgemm_kernel<1><<<dim3(1024/64, ROWS/128), 256, TG_SMEM>>>(xn, mlp_w1, mlp_b1, nullptr,
                                                               m1, ROWS, 1024, 256);
    // 8. MLP2 + gelu + residual -> out (tf32)
    tgemm_kernel<3><<<dim3(256/64, ROWS/128), 256, TG_SMEM>>>(m1, mlp_w2, mlp_b2, x1,
                                                              out, ROWS, 256, 1024);
}

// round 11
// speedup vs baseline: 2.0013x; 1.0625x over previous
#include <cuda_runtime.h>
#include <cuda_bf16.h>
#include <math.h>

// Shapes
#define BB 16
#define NN 256
#define DD 256
#define HH 8
#define HD 32
#define PD 4
#define RATIO 4
#define ROWS (BB*NN)            // 4096
#define PAIR_ROWS (BB*NN*NN)    // 1048576

// ---------------- scratch (device globals, no allocation) ----------------
__device__ float g_xn [ROWS*DD];        // 4 MB
__device__ float g_qkv[ROWS*3*DD];      // 12 MB
__device__ float g_biasT[BB*HH*NN*NN];  // 33.5 MB  [B,H,N,N]
__device__ float g_xa [ROWS*DD];        // 4 MB  [B,N,H*HD]
__device__ float g_x1 [ROWS*DD];        // 4 MB
__device__ float g_m1 [ROWS*RATIO*DD];  // 16 MB

// Branchless gelu via Abramowitz-Stegun 7.1.26 erf (|eps| <= 1.5e-7).
// ~12 instrs, 2 MUFU, no branches — vs libm erff's ~25 with branches.
__device__ __forceinline__ float gelu_exact(float x) {
    float z  = x * 0.70710678118654752f;
    float az = fabsf(z);
    float t  = __fdividef(1.0f, fmaf(0.3275911f, az, 1.0f));
    float p  = t*(0.254829592f + t*(-0.284496736f + t*(1.421413741f
                  + t*(-1.453152027f + t*1.061405429f))));
    float e  = __expf(-az*az);
    float erfv = copysignf(fmaf(-p, e, 1.0f), z);
    return 0.5f*x*(1.0f + erfv);
}

__device__ __forceinline__ unsigned f2tf32(float x) {
    unsigned r;
    asm("cvt.rna.tf32.f32 %0, %1;" : "=r"(r) : "f"(x));
    return r;
}

__device__ __forceinline__ void mma_tf32(
    float& c0, float& c1, float& c2, float& c3,
    unsigned a0, unsigned a1, unsigned a2, unsigned a3,
    unsigned b0, unsigned b1)
{
    asm volatile(
        "mma.sync.aligned.m16n8k8.row.col.f32.tf32.tf32.f32 "
        "{%0,%1,%2,%3}, {%4,%5,%6,%7}, {%8,%9}, {%0,%1,%2,%3};"
        : "+f"(c0), "+f"(c1), "+f"(c2), "+f"(c3)
        : "r"(a0), "r"(a1), "r"(a2), "r"(a3), "r"(b0), "r"(b1));
}

__device__ __forceinline__ unsigned sptr(const void* p) {
    return (unsigned)__cvta_generic_to_shared(p);
}
__device__ __forceinline__ void cp16(unsigned s, const float* g) {
    asm volatile("cp.async.cg.shared.global [%0], [%1], 16;" :: "r"(s), "l"(g));
}

// ---------------- pairwise MLP (tf32 tensor cores) ----------------
#define H1S 68   // smem row stride for h1 (conflict-free fragment loads)
__global__ __launch_bounds__(256) void pairwise_kernel(
    const float* __restrict__ u,
    const float* __restrict__ w1, const float* __restrict__ b1,
    const float* __restrict__ w2, const float* __restrict__ b2,
    const float* __restrict__ w3, const float* __restrict__ b3,
    float* __restrict__ biasOut)
{
    extern __shared__ float dsm[];
    unsigned* h1s = (unsigned*)dsm;                 // 128*68
    unsigned* w2f = h1s + 128*H1S;                  // 4096 (fragment layout)
    float*    w3s = (float*)(w2f + 4096);           // 512
    float*    b2s = w3s + 512;                      // 64
    float*    b3s = b2s + 64;                       // 8
    float*    w1s = b3s + 8;                        // 256
    float*    b1s = w1s + 256;                      // 64

    int tid = threadIdx.x;
    int lane = tid & 31, warp = tid >> 5;
    int tig = lane & 3, gid = lane >> 2;

    if (tid < 64)  b1s[tid] = b1[tid];
    if (tid < 64)  b2s[tid] = b2[tid];
    if (tid < 8)   b3s[tid] = b3[tid];
    w1s[tid] = w1[tid];
    for (int i = tid; i < 512; i += 256) w3s[i] = w3[i];
    for (int idx = tid; idx < 4096; idx += 256) {
        int tile = idx >> 6;          // kt*8 + nt
        int pos  = idx & 63;
        int l    = pos >> 1, which = pos & 1;
        int kt = tile >> 3, nt = tile & 7;
        int ltig = l & 3, lgid = l >> 2;
        int k = kt*8 + ltig + which*4;
        int n = nt*8 + lgid;
        w2f[tile*64 + l*2 + which] = f2tf32(w2[k*64 + n]);
    }

    {
        int row = tid >> 1;                 // 0..127
        int c0  = (tid & 1) * 32;
        long gr = (long)blockIdx.x * 128 + row;
        float4 uv = ((const float4*)u)[gr];
        unsigned* dst = h1s + row*H1S + c0;
#pragma unroll
        for (int cc = 0; cc < 32; cc += 4) {
            unsigned pk[4];
#pragma unroll
            for (int q = 0; q < 4; q++) {
                int c = c0 + cc + q;
                float t = b1s[c] + uv.x*w1s[c] + uv.y*w1s[64+c]
                                 + uv.z*w1s[128+c] + uv.w*w1s[192+c];
                pk[q] = f2tf32(gelu_exact(t));
            }
            *(uint4*)&dst[cc] = make_uint4(pk[0], pk[1], pk[2], pk[3]);
        }
    }
    __syncthreads();

    float c[8][4];
#pragma unroll
    for (int nt = 0; nt < 8; nt++)
#pragma unroll
        for (int q = 0; q < 4; q++) c[nt][q] = 0.f;

    const unsigned* h1w = h1s + (warp*16 + gid)*H1S;
#pragma unroll
    for (int kt = 0; kt < 8; kt++) {
        unsigned a0 = h1w[kt*8 + tig];
        unsigned a1 = h1w[8*H1S + kt*8 + tig];
        unsigned a2 = h1w[kt*8 + tig + 4];
        unsigned a3 = h1w[8*H1S + kt*8 + tig + 4];
        const uint2* bf = (const uint2*)(w2f + kt*8*64);
#pragma unroll
        for (int nt = 0; nt < 8; nt++) {
            uint2 b = bf[nt*32 + lane];
            mma_tf32(c[nt][0], c[nt][1], c[nt][2], c[nt][3],
                     a0, a1, a2, a3, b.x, b.y);
        }
    }

    float acc0[8], acc1[8];
#pragma unroll
    for (int h = 0; h < 8; h++) { acc0[h] = 0.f; acc1[h] = 0.f; }

#pragma unroll
    for (int nt = 0; nt < 8; nt++) {
        int col0 = nt*8 + tig*2;
        float g00 = gelu_exact(c[nt][0] + b2s[col0]);
        float g01 = gelu_exact(c[nt][1] + b2s[col0+1]);
        float g10 = gelu_exact(c[nt][2] + b2s[col0]);
        float g11 = gelu_exact(c[nt][3] + b2s[col0+1]);
        const float4* w3r = (const float4*)&w3s[col0*8];
        float4 wa0 = w3r[0], wa1 = w3r[1];
        float4 wb0 = w3r[2], wb1 = w3r[3];
        acc0[0] += g00*wa0.x + g01*wb0.x;  acc1[0] += g10*wa0.x + g11*wb0.x;
        acc0[1] += g00*wa0.y + g01*wb0.y;  acc1[1] += g10*wa0.y + g11*wb0.y;
        acc0[2] += g00*wa0.z + g01*wb0.z;  acc1[2] += g10*wa0.z + g11*wb0.z;
        acc0[3] += g00*wa0.w + g01*wb0.w;  acc1[3] += g10*wa0.w + g11*wb0.w;
        acc0[4] += g00*wa1.x + g01*wb1.x;  acc1[4] += g10*wa1.x + g11*wb1.x;
        acc0[5] += g00*wa1.y + g01*wb1.y;  acc1[5] += g10*wa1.y + g11*wb1.y;
        acc0[6] += g00*wa1.z + g01*wb1.z;  acc1[6] += g10*wa1.z + g11*wb1.z;
        acc0[7] += g00*wa1.w + g01*wb1.w;  acc1[7] += g10*wa1.w + g11*wb1.w;
    }

#pragma unroll
    for (int h = 0; h < 8; h++) {
        acc0[h] += __shfl_xor_sync(0xffffffffu, acc0[h], 1);
        acc1[h] += __shfl_xor_sync(0xffffffffu, acc1[h], 1);
    }
#pragma unroll
    for (int h = 0; h < 8; h++) {
        acc0[h] += __shfl_xor_sync(0xffffffffu, acc0[h], 2);
        acc1[h] += __shfl_xor_sync(0xffffffffu, acc1[h], 2);
    }

    long R0 = (long)blockIdx.x * 128 + warp*16 + gid;
    int b = (int)(R0 >> 16);
    int i = (int)((R0 >> 8) & 255);
    int j0 = (int)(R0 & 255);
    int hA = tig*2, hB = hA + 1;

    float oA0 = gelu_exact(acc0[hA] + b3s[hA]);
    float oB0 = gelu_exact(acc0[hB] + b3s[hB]);
    float oA1 = gelu_exact(acc1[hA] + b3s[hA]);
    float oB1 = gelu_exact(acc1[hB] + b3s[hB]);

    long baseA = ((long)(b*8 + hA) << 16) + (i << 8);
    long baseB = ((long)(b*8 + hB) << 16) + (i << 8);
    biasOut[baseA + j0]     = oA0;
    biasOut[baseB + j0]     = oB0;
    biasOut[baseA + j0 + 8] = oA1;
    biasOut[baseB + j0 + 8] = oB1;
}

// ---------------- LayerNorm ----------------
__global__ __launch_bounds__(256) void ln_kernel(
    const float* __restrict__ x, const float* __restrict__ g,
    const float* __restrict__ bb, float* __restrict__ out)
{
    __shared__ float red[16];
    int r = blockIdx.x, t = threadIdx.x;
    float v = x[r*256 + t];

    float s = v;
#pragma unroll
    for (int o = 16; o > 0; o >>= 1) s += __shfl_xor_sync(0xffffffffu, s, o);
    if ((t & 31) == 0) red[t >> 5] = s;
    __syncthreads();
    float mu = 0.f;
#pragma unroll
    for (int w = 0; w < 8; w++) mu += red[w];
    mu *= (1.0f/256.0f);

    float d = v - mu;
    float q = d*d;
#pragma unroll
    for (int o = 16; o > 0; o >>= 1) q += __shfl_xor_sync(0xffffffffu, q, o);
    if ((t & 31) == 0) red[8 + (t >> 5)] = q;
    __syncthreads();
    float var = 0.f;
#pragma unroll
    for (int w = 0; w < 8; w++) var += red[8 + w];
    var *= (1.0f/256.0f);

    out[r*256 + t] = d * rsqrtf(var + 1e-5f) * g[t] + bb[t];
}

// ---------------- tf32 tensor-core GEMM (cp.async double-buffered) ----------
#define AS_STRIDE 36
#define BS_STRIDE 72
#define A_BUF (128*AS_STRIDE)
#define B_BUF (32*BS_STRIDE)
#define TG_SMEM ((2*A_BUF + 2*B_BUF)*4)
template<int EPI>
__global__ __launch_bounds__(256, 2) void tgemm_kernel(
    const float* __restrict__ A, const float* __restrict__ Bm,
    const float* __restrict__ bias, const float* __restrict__ res,
    float* __restrict__ C, int M, int Nn, int K)
{
    extern __shared__ float tsm[];
    float* As = tsm;                 // 2 bufs of 128*36
    float* Bs = tsm + 2*A_BUF;       // 2 bufs of 32*72

    int tid = threadIdx.x;
    int lane = tid & 31, warp = tid >> 5;
    int tig = lane & 3, gid = lane >> 2;
    int warp_m = warp & 3, warp_n = warp >> 2;

    int row0 = blockIdx.y * 128;
    int col0 = blockIdx.x * 64;

    int ar = tid >> 1, ac = (tid & 1) * 16;
    int br = tid >> 3, bc = (tid & 7) * 8;

    const float* Ap = A + (long)(row0 + ar)*K + ac;
    const float* Bp = Bm + (long)br*Nn + col0 + bc;

    unsigned a_sb = sptr(&As[ar*AS_STRIDE + ac]);
    unsigned b_sb = sptr(&Bs[br*BS_STRIDE + bc]);

    float c[2][4][4];
#pragma unroll
    for (int mt = 0; mt < 2; mt++)
#pragma unroll
        for (int nt = 0; nt < 4; nt++)
#pragma unroll
            for (int q = 0; q < 4; q++) c[mt][nt][q] = 0.f;

    int iters = K >> 5;

    {
        const float* ag = Ap;
#pragma unroll
        for (int i = 0; i < 4; i++) cp16(a_sb + 16*i, ag + 4*i);
        const float* bg = Bp;
#pragma unroll
        for (int i = 0; i < 2; i++) cp16(b_sb + 16*i, bg + 4*i);
        asm volatile("cp.async.commit_group;");
    }

    for (int it = 0; it < iters; it++) {
        int buf = it & 1;
        if (it + 1 < iters) {
            int nbuf = buf ^ 1;
            const float* ag = Ap + (it + 1)*32;
#pragma unroll
            for (int i = 0; i < 4; i++) cp16(a_sb + nbuf*A_BUF*4 + 16*i, ag + 4*i);
            const float* bg = Bp + (long)(it + 1)*32*Nn;
#pragma unroll
            for (int i = 0; i < 2; i++) cp16(b_sb + nbuf*B_BUF*4 + 16*i, bg + 4*i);
            asm volatile("cp.async.commit_group;");
            asm volatile("cp.async.wait_group 1;");
        } else {
            asm volatile("cp.async.wait_group 0;");
        }
        __syncthreads();

        const float* aw0 = As + buf*A_BUF + (warp_m*32 + gid)*AS_STRIDE;
        const float* bw  = Bs + buf*B_BUF + warp_n*32 + gid;
#pragma unroll
        for (int kt = 0; kt < 4; kt++) {
            unsigned af[2][4];
#pragma unroll
            for (int mt = 0; mt < 2; mt++) {
                const float* aw = aw0 + mt*16*AS_STRIDE + kt*8;
                af[mt][0] = f2tf32(aw[tig]);
                af[mt][1] = f2tf32(aw[8*AS_STRIDE + tig]);
                af[mt][2] = f2tf32(aw[tig + 4]);
                af[mt][3] = f2tf32(aw[8*AS_STRIDE + tig + 4]);
            }
#pragma unroll
            for (int nt = 0; nt < 4; nt++) {
                const float* bww = bw + (kt*8 + tig)*BS_STRIDE + nt*8;
                unsigned b0 = f2tf32(bww[0]);
                unsigned b1 = f2tf32(bww[4*BS_STRIDE]);
#pragma unroll
                for (int mt = 0; mt < 2; mt++)
                    mma_tf32(c[mt][nt][0], c[mt][nt][1], c[mt][nt][2], c[mt][nt][3],
                             af[mt][0], af[mt][1], af[mt][2], af[mt][3], b0, b1);
            }
        }
        __syncthreads();
    }

#pragma unroll
    for (int mt = 0; mt < 2; mt++) {
#pragma unroll
        for (int half = 0; half < 2; half++) {
            int r = row0 + warp_m*32 + mt*16 + gid + half*8;
#pragma unroll
            for (int nt = 0; nt < 4; nt++) {
                int cc = col0 + warp_n*32 + nt*8 + tig*2;
                float v0 = c[mt][nt][half*2 + 0] + bias[cc];
                float v1 = c[mt][nt][half*2 + 1] + bias[cc + 1];
                if (EPI == 1 || EPI == 3) { v0 = gelu_exact(v0); v1 = gelu_exact(v1); }
                if (EPI == 2 || EPI == 3) {
                    const float2 rr = *(const float2*)&res[(long)r*Nn + cc];
                    v0 += rr.x; v1 += rr.y;
                }
                *(float2*)&C[(long)r*Nn + cc] = make_float2(v0, v1);
            }
        }
    }
}

// ---------------- Fused attention v4: low-reg, 2 blocks/SM -------------------
// grid = 256 (2 blocks per (b,h)), block = 512 (16 warps), <=64 regs.
// q staged in per-warp smem (broadcast reads); scores accumulate d4-outer.
#define KVSTRIDE 36
#define ATTN_SMEM ((256*KVSTRIDE*2 + 16*512 + 16*64)*4)
__global__ __launch_bounds__(512, 2) void attn_kernel(
    const float* __restrict__ qkv, const float* __restrict__ biasT,
    const unsigned char* __restrict__ mask, float* __restrict__ xa)
{
    extern __shared__ float sm[];
    float* Ks = sm;                        // 256*36
    float* Vs = Ks + 256*KVSTRIDE;         // 256*36
    float* Ps = Vs + 256*KVSTRIDE;         // 16*512
    float* Qs = Ps + 16*512;               // 16*64

    int tid  = threadIdx.x;
    int warp = tid >> 5, lane = tid & 31;
    int blk = blockIdx.x;
    int bh = blk >> 1, itile = blk & 1;
    int b = bh >> 3, h = bh & 7;

    const float* base = qkv + (long)b*256*768 + h*32;

    for (int idx = tid; idx < 2048; idx += 512) {
        int row = idx >> 3, d4 = (idx & 7) << 2;
        const float* src = base + (long)row*768;
        *(float4*)&Ks[row*KVSTRIDE + d4] = *(const float4*)(src + 256 + d4);
        *(float4*)&Vs[row*KVSTRIDE + d4] = *(const float4*)(src + 512 + d4);
    }
    __syncthreads();

    unsigned mk = 0;
#pragma unroll
    for (int c = 0; c < 8; c++)
        if (mask[b*256 + c*32 + lane]) mk |= (1u << c);

    float* p0 = Ps + warp*512;
    float* p1 = p0 + 256;
    float4* qs4 = (float4*)(Qs + warp*64);
    const float scale = 0.17677669529663687f;   // 1/sqrt(32)

    for (int ii = 0; ii < 8; ii += 2) {
        int i0 = itile*128 + warp*8 + ii, i1 = i0 + 1;

        // stage q (2 rows x 32 floats) into per-warp smem: one LDG.128/lane
        if (lane < 8)
            qs4[lane] = *((const float4*)(base + (long)i0*768) + lane);
        else if (lane < 16)
            qs4[lane] = *((const float4*)(base + (long)i1*768) + (lane - 8));
        __syncwarp();

        // bias prefetch (coalesced; consumed after score loop)
        const float* br0 = biasT + ((long)(bh*256 + i0) << 8);
        const float* br1 = biasT + ((long)(bh*256 + i1) << 8);
        float bb0[8], bb1[8];
#pragma unroll
        for (int c = 0; c < 8; c++) {
            bb0[c] = br0[c*32 + lane];
            bb1[c] = br1[c*32 + lane];
        }

        // scores: d4-outer, q via broadcast LDS; lane owns keys {c*32+lane}
        float a0[8], a1[8];
#pragma unroll
        for (int c = 0; c < 8; c++) { a0[c] = 0.f; a1[c] = 0.f; }
#pragma unroll
        for (int d4 = 0; d4 < 8; d4++) {
            float4 qq0 = qs4[d4];
            float4 qq1 = qs4[8 + d4];
#pragma unroll
            for (int c = 0; c < 8; c++) {
                float4 k4 = *(const float4*)&Ks[(c*32 + lane)*KVSTRIDE + d4*4];
                a0[c] += qq0.x*k4.x + qq0.y*k4.y + qq0.z*k4.z + qq0.w*k4.w;
                a1[c] += qq1.x*k4.x + qq1.y*k4.y + qq1.z*k4.z + qq1.w*k4.w;
            }
        }
#pragma unroll
        for (int c = 0; c < 8; c++) {
            a0[c] = a0[c]*scale + bb0[c];
            a1[c] = a1[c]*scale + bb1[c];
            if ((mk >> c) & 1) { a0[c] = -1e30f; a1[c] = -1e30f; }
        }

        // softmax (warp-local)
        float m0 = a0[0], m1 = a1[0];
#pragma unroll
        for (int c = 1; c < 8; c++) { m0 = fmaxf(m0, a0[c]); m1 = fmaxf(m1, a1[c]); }
#pragma unroll
        for (int o = 16; o > 0; o >>= 1) {
            m0 = fmaxf(m0, __shfl_xor_sync(0xffffffffu, m0, o));
            m1 = fmaxf(m1, __shfl_xor_sync(0xffffffffu, m1, o));
        }
        float z0 = 0.f, z1 = 0.f;
#pragma unroll
        for (int c = 0; c < 8; c++) {
            a0[c] = __expf(a0[c] - m0);  z0 += a0[c];
            a1[c] = __expf(a1[c] - m1);  z1 += a1[c];
        }
#pragma unroll
        for (int o = 16; o > 0; o >>= 1) {
            z0 += __shfl_xor_sync(0xffffffffu, z0, o);
            z1 += __shfl_xor_sync(0xffffffffu, z1, o);
        }
        float rz0 = 1.0f / z0, rz1 = 1.0f / z1;

#pragma unroll
        for (int c = 0; c < 8; c++) { p0[c*32 + lane] = a0[c]; p1[c*32 + lane] = a1[c]; }
        __syncwarp();

        // PV: lane owns output dim d = lane
        float acc0 = 0.f, acc1 = 0.f;
        const float4* p04 = (const float4*)p0;
        const float4* p14 = (const float4*)p1;
#pragma unroll
        for (int c = 0; c < 8; c++) {
#pragma unroll
            for (int j4 = 0; j4 < 8; j4++) {
                float4 P0 = p04[c*8 + j4];
                float4 P1 = p14[c*8 + j4];
                int j = c*32 + j4*4;
                float v0 = Vs[(j+0)*KVSTRIDE + lane];
                float v1 = Vs[(j+1)*KVSTRIDE + lane];
                float v2 = Vs[(j+2)*KVSTRIDE + lane];
                float v3 = Vs[(j+3)*KVSTRIDE + lane];
                acc0 += P0.x*v0 + P0.y*v1 + P0.z*v2 + P0.w*v3;
                acc1 += P1.x*v0 + P1.y*v1 + P1.z*v2 + P1.w*v3;
            }
        }
        __syncwarp();

        xa[(long)(b*256 + i0)*256 + h*32 + lane] = acc0 * rz0;
        xa[(long)(b*256 + i1)*256 + h*32 + lane] = acc1 * rz1;
    }
}

// ---------------- launch ----------------
extern "C" void kernel_launch(void* const* d_in, const int* in_sizes, int n_in,
                              void* d_out, int out_size)
{
    const float* x      = (const float*)d_in[0];
    const float* u      = (const float*)d_in[1];
    const unsigned char* mask = (const unsigned char*)d_in[2];
    const float* n1_g   = (const float*)d_in[3];
    const float* n1_b   = (const float*)d_in[4];
    const float* qkv_w  = (const float*)d_in[5];
    const float* qkv_b  = (const float*)d_in[6];
    const float* proj_w = (const float*)d_in[7];
    const float* proj_b = (const float*)d_in[8];
    const float* n2_g   = (const float*)d_in[9];
    const float* n2_b   = (const float*)d_in[10];
    const float* mlp_w1 = (const float*)d_in[11];
    const float* mlp_b1 = (const float*)d_in[12];
    const float* mlp_w2 = (const float*)d_in[13];
    const float* mlp_b2 = (const float*)d_in[14];
    const float* pw_w1  = (const float*)d_in[15];
    const float* pw_b1  = (const float*)d_in[16];
    const float* pw_w2  = (const float*)d_in[17];
    const float* pw_b2  = (const float*)d_in[18];
    const float* pw_w3  = (const float*)d_in[19];
    const float* pw_b3  = (const float*)d_in[20];
    float* out = (float*)d_out;

    float *xn, *qkvb, *biasT, *xa, *x1, *m1;
    cudaGetSymbolAddress((void**)&xn,    g_xn);
    cudaGetSymbolAddress((void**)&qkvb,  g_qkv);
    cudaGetSymbolAddress((void**)&biasT, g_biasT);
    cudaGetSymbolAddress((void**)&xa,    g_xa);
    cudaGetSymbolAddress((void**)&x1,    g_x1);
    cudaGetSymbolAddress((void**)&m1,    g_m1);

    // 1. pairwise MLP (tf32 mma) -> bias[B,H,N,N]
    int pw_smem = (128*H1S + 4096 + 512 + 64 + 8 + 256 + 64) * 4;
    cudaFuncSetAttribute(pairwise_kernel,
                         cudaFuncAttributeMaxDynamicSharedMemorySize, pw_smem);
    pairwise_kernel<<<PAIR_ROWS/128, 256, pw_smem>>>(u, pw_w1, pw_b1, pw_w2, pw_b2,
                                                     pw_w3, pw_b3, biasT);
    // 2. LN1
    ln_kernel<<<ROWS, 256>>>(x, n1_g, n1_b, xn);

    cudaFuncSetAttribute(tgemm_kernel<0>, cudaFuncAttributeMaxDynamicSharedMemorySize, TG_SMEM);
    cudaFuncSetAttribute(tgemm_kernel<1>, cudaFuncAttributeMaxDynamicSharedMemorySize, TG_SMEM);
    cudaFuncSetAttribute(tgemm_kernel<2>, cudaFuncAttributeMaxDynamicSharedMemorySize, TG_SMEM);
    cudaFuncSetAttribute(tgemm_kernel<3>, cudaFuncAttributeMaxDynamicSharedMemorySize, TG_SMEM);

    // 3. QKV GEMM (tf32)  [4096,256] x [256,768]
    tgemm_kernel<0><<<dim3(768/64, ROWS/128), 256, TG_SMEM>>>(xn, qkv_w, qkv_b, nullptr,
                                                              qkvb, ROWS, 768, 256);
    // 4. attention (2 blocks per head, true 2 blocks/SM)
    cudaFuncSetAttribute(attn_kernel, cudaFuncAttributeMaxDynamicSharedMemorySize,
                         ATTN_SMEM);
    attn_kernel<<<BB*HH*2, 512, ATTN_SMEM>>>(qkvb, biasT, mask, xa);
    // 5. proj + residual -> x1  (tf32)
    tgemm_kernel<2><<<dim3(256/64, ROWS/128), 256, TG_SMEM>>>(xa, proj_w, proj_b, x,
                                                              x1, ROWS, 256, 256);
    // 6. LN2
    ln_kernel<<<ROWS, 256>>>(x1, n2_g, n2_b, xn);
    // 7. MLP1 + gelu (tf32)
    tgemm_kernel<1><<<dim3(1024/64, ROWS/128), 256, TG_SMEM>>>(xn, mlp_w1, mlp_b1, nullptr,
                                                               m1, ROWS, 1024, 256);
    // 8. MLP2 + gelu + residual -> out (tf32)
    tgemm_kernel<3><<<dim3(256/64, ROWS/128), 256, TG_SMEM>>>(m1, mlp_w2, mlp_b2, x1,
                                                              out, ROWS, 256, 1024);
}